// round 1
// baseline (speedup 1.0000x reference)
#include <cuda_runtime.h>
#include <cstdint>
#include <cstddef>

#define DEVFN __device__ __forceinline__

constexpr int B = 16, N = 96, HID = 128, EF = 32, L = 4;
constexpr int BN = B * N;
constexpr float CUTOFF = 10.0f, RBF_GAMMA = 10.0f;
constexpr float PI_F = 3.14159265358979323846f;

// ---------------- scratch (device globals; no allocation allowed) ----------------
__device__ float g_mask[(size_t)BN * N * HID];  // 75.5 MB
__device__ float g_s0[BN * HID];
__device__ float g_s[BN * HID];
__device__ float g_s1[BN * HID];
__device__ float g_v[BN * 3 * HID];
__device__ float g_qv[BN * 3 * HID];
__device__ float g_kv[BN * 3 * HID];
__device__ float g_ea[BN * N];
__device__ float g_ev[BN * N * 3];

DEVFN float silu_f(float x) { return x / (1.0f + __expf(-x)); }

// block-wide sum with 128 threads (4 warps)
DEVFN float blksum128(float v, float* red) {
#pragma unroll
    for (int o = 16; o; o >>= 1) v += __shfl_xor_sync(0xffffffffu, v, o);
    if ((threadIdx.x & 31) == 0) red[threadIdx.x >> 5] = v;
    __syncthreads();
    float r = red[0] + red[1] + red[2] + red[3];
    __syncthreads();
    return r;
}

DEVFN void fma4(float4& a, float x, const float4 w) {
    a.x = fmaf(x, w.x, a.x);
    a.y = fmaf(x, w.y, a.y);
    a.z = fmaf(x, w.z, a.z);
    a.w = fmaf(x, w.w, a.w);
}

// ---------------- K0: s0 = LN(emb_table[z]) ----------------
__global__ void k_s0(const int* __restrict__ z, const float* __restrict__ emb) {
    int bi = blockIdx.x;
    int h = threadIdx.x;
    __shared__ float red[4];
    int zz = z[bi];
    float e = emb[zz * HID + h];
    float m = blksum128(e, red) * (1.0f / HID);
    float dx = e - m;
    float var = blksum128(dx * dx, red) * (1.0f / HID);
    g_s0[bi * HID + h] = dx * rsqrtf(var + 1e-5f);
}

// ---------------- K1: pairwise geometry + ef-projection -> mask ----------------
__global__ void k_geom(const int* __restrict__ z, const float* __restrict__ pos,
                       const float* __restrict__ Wef, const float* __restrict__ bef) {
    int i = blockIdx.x, b = blockIdx.y;
    int t = threadIdx.x;
    __shared__ float wS[EF * HID];
    __shared__ float bS[HID];
    __shared__ float efS[EF];
    for (int k = t; k < EF * HID; k += 128) wS[k] = Wef[k];
    bS[t] = bef[t];
    float padi = (z[b * N + i] != 0) ? 1.0f : 0.0f;
    float xi = pos[(b * N + i) * 3 + 0];
    float yi = pos[(b * N + i) * 3 + 1];
    float zi = pos[(b * N + i) * 3 + 2];
    __syncthreads();
    for (int j = 0; j < N; j++) {
        float padj = (z[b * N + j] != 0) ? 1.0f : 0.0f;
        float dx = pos[(b * N + j) * 3 + 0] - xi;
        float dy = pos[(b * N + j) * 3 + 1] - yi;
        float dz = pos[(b * N + j) * 3 + 2] - zi;
        float d2 = dx * dx + dy * dy + dz * dz;
        float d = sqrtf(d2 + 1e-12f);
        float pm = padi * padj * ((i != j) ? 1.0f : 0.0f);
        float ea = (d < CUTOFF) ? 0.5f * (cosf(PI_F * d * (1.0f / CUTOFF)) + 1.0f) * pm : 0.0f;
        float inv = pm / (d + 1e-12f);
        if (t == 0) {
            size_t pidx = (size_t)(b * N + i) * N + j;
            g_ea[pidx] = ea;
            g_ev[pidx * 3 + 0] = dx * inv;
            g_ev[pidx * 3 + 1] = dy * inv;
            g_ev[pidx * 3 + 2] = dz * inv;
        }
        if (t < EF) {
            float c = t * (CUTOFF / (EF - 1));
            float dd = d - c;
            efS[t] = __expf(-RBF_GAMMA * dd * dd) * pm;
        }
        __syncthreads();
        float acc = bS[t];
#pragma unroll
        for (int k = 0; k < EF; k++) acc = fmaf(efS[k], wS[k * HID + t], acc);
        g_mask[((size_t)(b * N + i) * N + j) * HID + t] = silu_f(acc) * ea;
        __syncthreads();
    }
}

// ---------------- K2: NeighborEmb  s = s0 + sum_j mask_ij * s0_j ----------------
__global__ void k_nemb() {
    int i = blockIdx.x, b = blockIdx.y, h = threadIdx.x;
    int bi = b * N + i;
    float acc = g_s0[bi * HID + h];
    const float* mrow = &g_mask[(size_t)bi * N * HID + h];
#pragma unroll 4
    for (int j = 0; j < N; j++) acc = fmaf(mrow[(size_t)j * HID], g_s0[(b * N + j) * HID + h], acc);
    g_s[bi * HID + h] = acc;
}

// ---------------- shared: out(g_s1) = silu(LN(g_s @ W + bv)) ----------------
__global__ void k_lin(const float* __restrict__ W, const float* __restrict__ bv) {
    int bi = blockIdx.y * N + blockIdx.x;
    int t = threadIdx.x;
    __shared__ float sS[HID];
    __shared__ float red[4];
    sS[t] = g_s[bi * HID + t];
    __syncthreads();
    float acc = bv[t];
#pragma unroll 8
    for (int h = 0; h < HID; h++) acc = fmaf(sS[h], W[h * HID + t], acc);
    float m = blksum128(acc, red) * (1.0f / HID);
    float dx = acc - m;
    float var = blksum128(dx * dx, red) * (1.0f / HID);
    g_s1[bi * HID + t] = silu_f(dx * rsqrtf(var + 1e-5f));
}

// ---------------- K4: v_i = sum_j mask_ij * s1_j * ev_ij ----------------
__global__ void k_v() {
    int i = blockIdx.x, b = blockIdx.y, h = threadIdx.x;
    int bi = b * N + i;
    float a0 = 0.0f, a1 = 0.0f, a2 = 0.0f;
    const float* mrow = &g_mask[(size_t)bi * N * HID + h];
    const float* evrow = &g_ev[(size_t)bi * N * 3];
#pragma unroll 4
    for (int j = 0; j < N; j++) {
        float w = mrow[(size_t)j * HID] * g_s1[(b * N + j) * HID + h];
        a0 = fmaf(w, evrow[j * 3 + 0], a0);
        a1 = fmaf(w, evrow[j * 3 + 1], a1);
        a2 = fmaf(w, evrow[j * 3 + 2], a2);
    }
    g_v[(bi * 3 + 0) * HID + h] = a0;
    g_v[(bi * 3 + 1) * HID + h] = a1;
    g_v[(bi * 3 + 2) * HID + h] = a2;
}

// ---------------- K5: qv = v@Wq, kv = v@Wk ----------------
__global__ void k_qk(const float* __restrict__ Wq, const float* __restrict__ Wk) {
    int bi = blockIdx.y * N + blockIdx.x;
    int t = threadIdx.x;
    __shared__ float vS[3 * HID];
    for (int k = t; k < 3 * HID; k += 128) vS[k] = g_v[bi * 3 * HID + k];
    __syncthreads();
#pragma unroll
    for (int k = 0; k < 3; k++) {
        float aq = 0.0f, ak = 0.0f;
#pragma unroll 8
        for (int h = 0; h < HID; h++) {
            float vv = vS[k * HID + h];
            aq = fmaf(vv, Wq[h * HID + t], aq);
            ak = fmaf(vv, Wk[h * HID + t], ak);
        }
        g_qv[(bi * 3 + k) * HID + t] = aq;
        g_kv[(bi * 3 + k) * HID + t] = ak;
    }
}

// ---------------- K6: fused directional MLP: mask *= dp ----------------
// per (b,i): dirf(96x256) in smem -> t1 = silu(dirf@Wd1+b) -> dp = silu(t1@Wd2+b)
constexpr int SMEM_DIR_FLOATS = 2 * N * 256 + 2 * 3 * HID + N + N * 3;  // 50304
constexpr int SMEM_DIR_BYTES = SMEM_DIR_FLOATS * 4;                     // 201216

__global__ void __launch_bounds__(256, 1) k_dir(const float* __restrict__ Wd1,
                                                const float* __restrict__ bd1,
                                                const float* __restrict__ Wd2,
                                                const float* __restrict__ bd2) {
    int i = blockIdx.x, b = blockIdx.y;
    int bi = b * N + i;
    int t = threadIdx.x;
    extern __shared__ float sm[];
    float* dirfS = sm;                   // 96*256
    float* t1S = dirfS + N * 256;        // 96*256
    float* vS = t1S + N * 256;           // 384
    float* kvS = vS + 3 * HID;           // 384
    float* eaS = kvS + 3 * HID;          // 96
    float* evS = eaS + N;                // 288

    for (int k = t; k < 3 * HID; k += 256) {
        vS[k] = g_v[bi * 3 * HID + k];
        kvS[k] = g_kv[bi * 3 * HID + k];
    }
    for (int k = t; k < N; k += 256) eaS[k] = g_ea[(size_t)bi * N + k];
    for (int k = t; k < N * 3; k += 256) evS[k] = g_ev[(size_t)bi * N * 3 + k];
    __syncthreads();

    // phase 2: dirf = concat(dir2, dir3) * ea
    for (int e = t; e < N * HID; e += 256) {
        int j = e >> 7, h = e & 127;
        float e0 = evS[j * 3 + 0], e1 = evS[j * 3 + 1], e2 = evS[j * 3 + 2];
        float d2v = vS[h] * e0 + vS[HID + h] * e1 + vS[2 * HID + h] * e2;
        const float* qj = &g_qv[(size_t)(b * N + j) * 3 * HID + h];
        float d3v = qj[0] * kvS[h] + qj[HID] * kvS[HID + h] + qj[2 * HID] * kvS[2 * HID + h];
        float ea = eaS[j];
        dirfS[j * 256 + h] = d2v * ea;
        dirfS[j * 256 + 128 + h] = d3v * ea;
    }
    __syncthreads();

    // phase 3: t1 = silu(dirf @ Wd1 + bd1)   (96x256 @ 256x256)
    {
        int cg = t & 63, jseg = t >> 6;  // 64 col-groups x 4 j-segments
        int o = cg * 4;
        float4 bb = *(const float4*)(bd1 + o);
        for (int jt = jseg * 24; jt < jseg * 24 + 24; jt += 12) {
            float4 acc[12];
#pragma unroll
            for (int jj = 0; jj < 12; jj++) acc[jj] = make_float4(0.f, 0.f, 0.f, 0.f);
            for (int k = 0; k < 256; k += 4) {
                const float* wp = Wd1 + k * 256 + o;
                float4 w0 = *(const float4*)(wp);
                float4 w1 = *(const float4*)(wp + 256);
                float4 w2 = *(const float4*)(wp + 512);
                float4 w3 = *(const float4*)(wp + 768);
#pragma unroll
                for (int jj = 0; jj < 12; jj++) {
                    float4 xv = *(const float4*)&dirfS[(jt + jj) * 256 + k];
                    float4 a = acc[jj];
                    fma4(a, xv.x, w0);
                    fma4(a, xv.y, w1);
                    fma4(a, xv.z, w2);
                    fma4(a, xv.w, w3);
                    acc[jj] = a;
                }
            }
#pragma unroll
            for (int jj = 0; jj < 12; jj++) {
                float4 a = acc[jj];
                a.x = silu_f(a.x + bb.x);
                a.y = silu_f(a.y + bb.y);
                a.z = silu_f(a.z + bb.z);
                a.w = silu_f(a.w + bb.w);
                *(float4*)&t1S[(jt + jj) * 256 + o] = a;
            }
        }
    }
    __syncthreads();

    // phase 4: dp = silu(t1 @ Wd2 + bd2); mask *= dp   (96x256 @ 256x128)
    {
        int cg = t & 31, jseg = t >> 5;  // 32 col-groups x 8 j-segments
        int o = cg * 4;
        int jt = jseg * 12;
        float4 bb = *(const float4*)(bd2 + o);
        float4 acc[12];
#pragma unroll
        for (int jj = 0; jj < 12; jj++) acc[jj] = make_float4(0.f, 0.f, 0.f, 0.f);
        for (int k = 0; k < 256; k += 4) {
            const float* wp = Wd2 + k * 128 + o;
            float4 w0 = *(const float4*)(wp);
            float4 w1 = *(const float4*)(wp + 128);
            float4 w2 = *(const float4*)(wp + 256);
            float4 w3 = *(const float4*)(wp + 384);
#pragma unroll
            for (int jj = 0; jj < 12; jj++) {
                float4 xv = *(const float4*)&t1S[(jt + jj) * 256 + k];
                float4 a = acc[jj];
                fma4(a, xv.x, w0);
                fma4(a, xv.y, w1);
                fma4(a, xv.z, w2);
                fma4(a, xv.w, w3);
                acc[jj] = a;
            }
        }
#pragma unroll
        for (int jj = 0; jj < 12; jj++) {
            int j = jt + jj;
            float4 a = acc[jj];
            size_t midx = ((size_t)bi * N + j) * HID + o;
            float4 mo = *(const float4*)&g_mask[midx];
            mo.x *= silu_f(a.x + bb.x);
            mo.y *= silu_f(a.y + bb.y);
            mo.z *= silu_f(a.z + bb.z);
            mo.w *= silu_f(a.w + bb.w);
            *(float4*)&g_mask[midx] = mo;
        }
    }
}

// ---------------- K7b: s += sum_j mask_ij * s1_j ----------------
__global__ void k_agg() {
    int i = blockIdx.x, b = blockIdx.y, h = threadIdx.x;
    int bi = b * N + i;
    float acc = g_s[bi * HID + h];
    const float* mrow = &g_mask[(size_t)bi * N * HID + h];
#pragma unroll 4
    for (int j = 0; j < N; j++) acc = fmaf(mrow[(size_t)j * HID], g_s1[(b * N + j) * HID + h], acc);
    g_s[bi * HID + h] = acc;
}

// ---------------- K8: readout ----------------
__global__ void k_read(const int* __restrict__ z, const float* __restrict__ Wout,
                       const float* __restrict__ bout, float* __restrict__ out) {
    int b = blockIdx.x;
    int h = threadIdx.x;
    __shared__ float red[4];
    float acc = 0.0f;
    for (int i = 0; i < N; i++) {
        if (z[b * N + i] != 0) acc += g_s[(b * N + i) * HID + h];
    }
    float p = acc * Wout[h];
    float s = blksum128(p, red);
    if (h == 0) out[b] = s + bout[0];
}

// ---------------- launch ----------------
extern "C" void kernel_launch(void* const* d_in, const int* in_sizes, int n_in,
                              void* d_out, int out_size) {
    const int* z = (const int*)d_in[0];
    const float* pos = (const float*)d_in[1];
    const float* emb = (const float*)d_in[2];
    const float* Wef = (const float*)d_in[3];
    const float* bef = (const float*)d_in[4];
    const float* Ws2v = (const float*)d_in[5];
    const float* bs2v = (const float*)d_in[6];
    const float* Wq = (const float*)d_in[7];
    const float* Wk = (const float*)d_in[8];
    const float* Wd1 = (const float*)d_in[9];
    const float* bd1 = (const float*)d_in[10];
    const float* Wd2 = (const float*)d_in[11];
    const float* bd2 = (const float*)d_in[12];
    const float* Wint = (const float*)d_in[13];
    const float* bint = (const float*)d_in[14];
    const float* Wout = (const float*)d_in[15];
    const float* bout = (const float*)d_in[16];
    float* out = (float*)d_out;

    cudaFuncSetAttribute(k_dir, cudaFuncAttributeMaxDynamicSharedMemorySize, SMEM_DIR_BYTES);

    dim3 g(N, B);
    k_s0<<<BN, 128>>>(z, emb);
    k_geom<<<g, 128>>>(z, pos, Wef, bef);
    k_nemb<<<g, 128>>>();
    k_lin<<<g, 128>>>(Ws2v, bs2v);          // -> g_s1
    k_v<<<g, 128>>>();
    k_qk<<<g, 128>>>(Wq, Wk);
    k_dir<<<g, 256, SMEM_DIR_BYTES>>>(Wd1, bd1, Wd2, bd2);
    for (int l = 0; l < L; l++) {
        k_lin<<<g, 128>>>(Wint + (size_t)l * HID * HID, bint + (size_t)l * HID);
        k_agg<<<g, 128>>>();
    }
    k_read<<<B, 128>>>(z, Wout, bout, out);
}

// round 2
// speedup vs baseline: 1.6258x; 1.6258x over previous
#include <cuda_runtime.h>
#include <cstdint>
#include <cstddef>

#define DEVFN __device__ __forceinline__

constexpr int B = 16, N = 96, HID = 128, EF = 32, L = 4;
constexpr int BN = B * N;
constexpr float CUTOFF = 10.0f, RBF_GAMMA = 10.0f;
constexpr float PI_F = 3.14159265358979323846f;

// ---------------- scratch (device globals; no allocation allowed) ----------------
__device__ float g_mask[(size_t)BN * N * HID];  // 75.5 MB
__device__ float g_s0[BN * HID];
__device__ float g_s[BN * HID];
__device__ float g_s1[BN * HID];
__device__ float g_v[BN * 3 * HID];
__device__ float g_qv[BN * 3 * HID];
__device__ float g_kv[BN * 3 * HID];
__device__ float g_ea[BN * N];
__device__ float g_ev[BN * N * 3];

DEVFN float silu_f(float x) { return x / (1.0f + __expf(-x)); }

DEVFN void fma4(float4& a, float x, const float4 w) {
    a.x = fmaf(x, w.x, a.x);
    a.y = fmaf(x, w.y, a.y);
    a.z = fmaf(x, w.z, a.z);
    a.w = fmaf(x, w.w, a.w);
}

DEVFN uint32_t f2tf(float x) {
    uint32_t r;
    asm("cvt.rna.tf32.f32 %0, %1;" : "=r"(r) : "f"(x));
    return r;
}
DEVFN float tfbits(float x) { return __uint_as_float(f2tf(x)); }

DEVFN void mma8(float c[4], uint32_t a0, uint32_t a1, uint32_t a2, uint32_t a3,
                uint32_t b0, uint32_t b1) {
    asm volatile(
        "mma.sync.aligned.m16n8k8.row.col.f32.tf32.tf32.f32 "
        "{%0,%1,%2,%3},{%4,%5,%6,%7},{%8,%9},{%0,%1,%2,%3};\n"
        : "+f"(c[0]), "+f"(c[1]), "+f"(c[2]), "+f"(c[3])
        : "r"(a0), "r"(a1), "r"(a2), "r"(a3), "r"(b0), "r"(b1));
}

// block-wide sum with 128 threads (4 warps)
DEVFN float blksum128(float v, float* red) {
#pragma unroll
    for (int o = 16; o; o >>= 1) v += __shfl_xor_sync(0xffffffffu, v, o);
    if ((threadIdx.x & 31) == 0) red[threadIdx.x >> 5] = v;
    __syncthreads();
    float r = red[0] + red[1] + red[2] + red[3];
    __syncthreads();
    return r;
}

// ---------------- K0: s0 = LN(emb_table[z]) ----------------
__global__ void k_s0(const int* __restrict__ z, const float* __restrict__ emb) {
    int bi = blockIdx.x;
    int h = threadIdx.x;
    __shared__ float red[4];
    int zz = z[bi];
    float e = emb[zz * HID + h];
    float m = blksum128(e, red) * (1.0f / HID);
    float dx = e - m;
    float var = blksum128(dx * dx, red) * (1.0f / HID);
    g_s0[bi * HID + h] = dx * rsqrtf(var + 1e-5f);
}

// ---------------- K1: geometry + ef-proj -> mask, fused NeighborEmb -> s ----------------
__global__ void __launch_bounds__(128) k_geomne(const int* __restrict__ z,
                                                const float* __restrict__ pos,
                                                const float* __restrict__ Wef,
                                                const float* __restrict__ bef) {
    int i = blockIdx.x, b = blockIdx.y;
    int bi = b * N + i;
    int t = threadIdx.x, w = t >> 5, lane = t & 31;
    __shared__ float wS[EF * HID];
    __shared__ float bS[HID];
    __shared__ float pS[4][HID];
    for (int k = t; k < EF * HID; k += 128) wS[k] = Wef[k];
    bS[t] = bef[t];
    float padi = (z[bi] != 0) ? 1.0f : 0.0f;
    float xi = pos[bi * 3 + 0];
    float yi = pos[bi * 3 + 1];
    float zi = pos[bi * 3 + 2];
    __syncthreads();
    float4 bb = *(const float4*)&bS[lane * 4];
    float4 sacc = make_float4(0.f, 0.f, 0.f, 0.f);
    for (int j = w; j < N; j += 4) {
        float padj = (z[b * N + j] != 0) ? 1.0f : 0.0f;
        float dx = pos[(b * N + j) * 3 + 0] - xi;
        float dy = pos[(b * N + j) * 3 + 1] - yi;
        float dz = pos[(b * N + j) * 3 + 2] - zi;
        float d = sqrtf(dx * dx + dy * dy + dz * dz + 1e-12f);
        float pm = padi * padj * ((i != j) ? 1.0f : 0.0f);
        float ea = (d < CUTOFF) ? 0.5f * (cosf(PI_F * d * (1.0f / CUTOFF)) + 1.0f) * pm : 0.0f;
        float inv = pm / (d + 1e-12f);
        float cc = lane * (CUTOFF / (EF - 1));
        float dd = d - cc;
        float efv = __expf(-RBF_GAMMA * dd * dd) * pm;
        float4 acc = bb;
#pragma unroll
        for (int k = 0; k < EF; k++) {
            float e = __shfl_sync(0xffffffffu, efv, k);
            float4 w4 = *(const float4*)&wS[k * HID + lane * 4];
            fma4(acc, e, w4);
        }
        float4 mv;
        mv.x = silu_f(acc.x) * ea;
        mv.y = silu_f(acc.y) * ea;
        mv.z = silu_f(acc.z) * ea;
        mv.w = silu_f(acc.w) * ea;
        *(float4*)&g_mask[((size_t)bi * N + j) * HID + lane * 4] = mv;
        float4 s0j = *(const float4*)&g_s0[(b * N + j) * HID + lane * 4];
        sacc.x = fmaf(mv.x, s0j.x, sacc.x);
        sacc.y = fmaf(mv.y, s0j.y, sacc.y);
        sacc.z = fmaf(mv.z, s0j.z, sacc.z);
        sacc.w = fmaf(mv.w, s0j.w, sacc.w);
        if (lane == 0) {
            size_t pidx = (size_t)bi * N + j;
            g_ea[pidx] = ea;
            g_ev[pidx * 3 + 0] = dx * inv;
            g_ev[pidx * 3 + 1] = dy * inv;
            g_ev[pidx * 3 + 2] = dz * inv;
        }
    }
    *(float4*)&pS[w][lane * 4] = sacc;
    __syncthreads();
    float s = g_s0[bi * HID + t] + pS[0][t] + pS[1][t] + pS[2][t] + pS[3][t];
    g_s[bi * HID + t] = s;
}

// ---------------- K2: batched  s1 = silu(LN(s @ W + b)), 8 atoms/block ----------------
constexpr int LIN_R = 8;
constexpr int SMEM_LIN_BYTES = (HID * HID + 2 * LIN_R * HID + 16) * 4;
__global__ void __launch_bounds__(128) k_lin8(const float* __restrict__ W,
                                              const float* __restrict__ bv) {
    extern __shared__ float sm[];
    float* wS = sm;
    float* sS = wS + HID * HID;
    float* oS = sS + LIN_R * HID;
    float* mS = oS + LIN_R * HID;
    float* vS = mS + 8;
    int t = threadIdx.x, w = t >> 5, lane = t & 31;
    int base = blockIdx.x * LIN_R;
    for (int k = t; k < HID * HID; k += 128) wS[k] = W[k];
    for (int k = t; k < LIN_R * HID; k += 128) sS[k] = g_s[base * HID + k];
    __syncthreads();
    float acc[LIN_R];
    float bb = bv[t];
#pragma unroll
    for (int r = 0; r < LIN_R; r++) acc[r] = bb;
#pragma unroll 4
    for (int h = 0; h < HID; h++) {
        float wv = wS[h * HID + t];
#pragma unroll
        for (int r = 0; r < LIN_R; r++) acc[r] = fmaf(sS[r * HID + h], wv, acc[r]);
    }
#pragma unroll
    for (int r = 0; r < LIN_R; r++) oS[r * HID + t] = acc[r];
    __syncthreads();
    for (int r = w; r < LIN_R; r += 4) {
        float x0 = oS[r * HID + lane], x1 = oS[r * HID + lane + 32];
        float x2 = oS[r * HID + lane + 64], x3 = oS[r * HID + lane + 96];
        float s = x0 + x1 + x2 + x3;
#pragma unroll
        for (int o = 16; o; o >>= 1) s += __shfl_xor_sync(0xffffffffu, s, o);
        float mean = s * (1.0f / HID);
        float q0 = x0 - mean, q1 = x1 - mean, q2 = x2 - mean, q3 = x3 - mean;
        float q = q0 * q0 + q1 * q1 + q2 * q2 + q3 * q3;
#pragma unroll
        for (int o = 16; o; o >>= 1) q += __shfl_xor_sync(0xffffffffu, q, o);
        if (lane == 0) {
            mS[r] = mean;
            vS[r] = rsqrtf(q * (1.0f / HID) + 1e-5f);
        }
    }
    __syncthreads();
#pragma unroll
    for (int r = 0; r < LIN_R; r++) {
        float val = (oS[r * HID + t] - mS[r]) * vS[r];
        g_s1[(base + r) * HID + t] = silu_f(val);
    }
}

// ---------------- K3: v_i = sum_j mask_ij * s1_j * ev_ij ----------------
__global__ void k_v() {
    int i = blockIdx.x, b = blockIdx.y, h = threadIdx.x;
    int bi = b * N + i;
    float a0 = 0.0f, a1 = 0.0f, a2 = 0.0f;
    const float* mrow = &g_mask[(size_t)bi * N * HID + h];
    const float* evrow = &g_ev[(size_t)bi * N * 3];
#pragma unroll 4
    for (int j = 0; j < N; j++) {
        float wv = mrow[(size_t)j * HID] * g_s1[(b * N + j) * HID + h];
        a0 = fmaf(wv, evrow[j * 3 + 0], a0);
        a1 = fmaf(wv, evrow[j * 3 + 1], a1);
        a2 = fmaf(wv, evrow[j * 3 + 2], a2);
    }
    g_v[(bi * 3 + 0) * HID + h] = a0;
    g_v[(bi * 3 + 1) * HID + h] = a1;
    g_v[(bi * 3 + 2) * HID + h] = a2;
}

// ---------------- K4: batched qv/kv, 8 atoms/block ----------------
constexpr int SMEM_QK_BYTES = (2 * HID * HID + LIN_R * 3 * HID) * 4;
__global__ void __launch_bounds__(128) k_qk8(const float* __restrict__ Wq,
                                             const float* __restrict__ Wk) {
    extern __shared__ float sm[];
    float* wqS = sm;
    float* wkS = wqS + HID * HID;
    float* vS = wkS + HID * HID;
    int t = threadIdx.x;
    int base = blockIdx.x * LIN_R;
    for (int k = t; k < HID * HID; k += 128) {
        wqS[k] = Wq[k];
        wkS[k] = Wk[k];
    }
    for (int k = t; k < LIN_R * 3 * HID; k += 128) vS[k] = g_v[base * 3 * HID + k];
    __syncthreads();
#pragma unroll
    for (int k3 = 0; k3 < 3; k3++) {
        float aq[LIN_R], ak[LIN_R];
#pragma unroll
        for (int r = 0; r < LIN_R; r++) { aq[r] = 0.f; ak[r] = 0.f; }
#pragma unroll 4
        for (int h = 0; h < HID; h++) {
            float wq = wqS[h * HID + t];
            float wk = wkS[h * HID + t];
#pragma unroll
            for (int r = 0; r < LIN_R; r++) {
                float vv = vS[r * 3 * HID + k3 * HID + h];
                aq[r] = fmaf(vv, wq, aq[r]);
                ak[r] = fmaf(vv, wk, ak[r]);
            }
        }
#pragma unroll
        for (int r = 0; r < LIN_R; r++) {
            g_qv[((base + r) * 3 + k3) * HID + t] = aq[r];
            g_kv[((base + r) * 3 + k3) * HID + t] = ak[r];
        }
    }
}

// ---------------- K5: fused directional MLP with tf32 mma: mask *= dp ----------------
constexpr int P = 260;  // padded pitch (floats); 260 % 32 = 4 -> conflict-free mma frags
constexpr int SMEM_DIR_FLOATS = 2 * N * P + 2 * 3 * HID + N + 3 * N;
constexpr int SMEM_DIR_BYTES = SMEM_DIR_FLOATS * 4;  // ~204 KB

__global__ void __launch_bounds__(256, 1) k_dir(const float* __restrict__ Wd1,
                                                const float* __restrict__ bd1,
                                                const float* __restrict__ Wd2,
                                                const float* __restrict__ bd2) {
    int i = blockIdx.x, b = blockIdx.y;
    int bi = b * N + i;
    int t = threadIdx.x, w = t >> 5, lane = t & 31;
    int gr = lane >> 2, kr = lane & 3;
    extern __shared__ float sm[];
    float* dirfS = sm;             // 96 x P (tf32 bits)
    float* t1S = dirfS + N * P;    // 96 x P (tf32 bits)
    float* vS = t1S + N * P;
    float* kvS = vS + 3 * HID;
    float* eaS = kvS + 3 * HID;
    float* evS = eaS + N;

    for (int k = t; k < 3 * HID; k += 256) {
        vS[k] = g_v[bi * 3 * HID + k];
        kvS[k] = g_kv[bi * 3 * HID + k];
    }
    if (t < N) eaS[t] = g_ea[(size_t)bi * N + t];
    for (int k = t; k < 3 * N; k += 256) evS[k] = g_ev[(size_t)bi * N * 3 + k];
    __syncthreads();

    // dirf = concat(dir2, dir3) * ea, stored as tf32 bits
    for (int e = t; e < N * HID; e += 256) {
        int j = e >> 7, h = e & 127;
        float e0 = evS[j * 3 + 0], e1 = evS[j * 3 + 1], e2 = evS[j * 3 + 2];
        float d2v = vS[h] * e0 + vS[HID + h] * e1 + vS[2 * HID + h] * e2;
        const float* qj = &g_qv[(size_t)(b * N + j) * 3 * HID + h];
        float d3v = qj[0] * kvS[h] + qj[HID] * kvS[HID + h] + qj[2 * HID] * kvS[2 * HID + h];
        float ea = eaS[j];
        dirfS[j * P + h] = tfbits(d2v * ea);
        dirfS[j * P + 128 + h] = tfbits(d3v * ea);
    }
    __syncthreads();

    // phase 3: t1 = silu(dirf(96x256) @ Wd1(256x256) + bd1); warp w owns 32 cols
    {
        int n0 = w * 32;
        float acc[6][4][4];
#pragma unroll
        for (int mt = 0; mt < 6; mt++)
#pragma unroll
            for (int ns = 0; ns < 4; ns++)
#pragma unroll
                for (int c = 0; c < 4; c++) acc[mt][ns][c] = 0.f;
        uint32_t bc[4][2], bn[4][2];
#pragma unroll
        for (int ns = 0; ns < 4; ns++) {
            const float* wp = Wd1 + kr * 256 + n0 + ns * 8 + gr;
            bc[ns][0] = f2tf(wp[0]);
            bc[ns][1] = f2tf(wp[1024]);
        }
        for (int ks = 0; ks < 32; ks++) {
            int k0 = ks * 8;
            if (ks < 31) {
#pragma unroll
                for (int ns = 0; ns < 4; ns++) {
                    const float* wp = Wd1 + (k0 + 8 + kr) * 256 + n0 + ns * 8 + gr;
                    bn[ns][0] = f2tf(wp[0]);
                    bn[ns][1] = f2tf(wp[1024]);
                }
            }
#pragma unroll
            for (int mt = 0; mt < 6; mt++) {
                const float* ap = dirfS + (mt * 16 + gr) * P + k0 + kr;
                uint32_t a0 = __float_as_uint(ap[0]);
                uint32_t a1 = __float_as_uint(ap[8 * P]);
                uint32_t a2 = __float_as_uint(ap[4]);
                uint32_t a3 = __float_as_uint(ap[8 * P + 4]);
#pragma unroll
                for (int ns = 0; ns < 4; ns++)
                    mma8(acc[mt][ns], a0, a1, a2, a3, bc[ns][0], bc[ns][1]);
            }
#pragma unroll
            for (int ns = 0; ns < 4; ns++) {
                bc[ns][0] = bn[ns][0];
                bc[ns][1] = bn[ns][1];
            }
        }
#pragma unroll
        for (int ns = 0; ns < 4; ns++) {
            int cb = n0 + ns * 8 + 2 * kr;
            float bv0 = bd1[cb], bv1 = bd1[cb + 1];
#pragma unroll
            for (int mt = 0; mt < 6; mt++) {
                int r0 = mt * 16 + gr;
                t1S[r0 * P + cb] = tfbits(silu_f(acc[mt][ns][0] + bv0));
                t1S[r0 * P + cb + 1] = tfbits(silu_f(acc[mt][ns][1] + bv1));
                t1S[(r0 + 8) * P + cb] = tfbits(silu_f(acc[mt][ns][2] + bv0));
                t1S[(r0 + 8) * P + cb + 1] = tfbits(silu_f(acc[mt][ns][3] + bv1));
            }
        }
    }
    __syncthreads();

    // phase 4: dp = silu(t1(96x256) @ Wd2(256x128) + bd2); mask *= dp; warp w owns 16 cols
    {
        int n0 = w * 16;
        float acc[6][2][4];
#pragma unroll
        for (int mt = 0; mt < 6; mt++)
#pragma unroll
            for (int ns = 0; ns < 2; ns++)
#pragma unroll
                for (int c = 0; c < 4; c++) acc[mt][ns][c] = 0.f;
        uint32_t bc[2][2], bn[2][2];
#pragma unroll
        for (int ns = 0; ns < 2; ns++) {
            const float* wp = Wd2 + kr * 128 + n0 + ns * 8 + gr;
            bc[ns][0] = f2tf(wp[0]);
            bc[ns][1] = f2tf(wp[512]);
        }
        for (int ks = 0; ks < 32; ks++) {
            int k0 = ks * 8;
            if (ks < 31) {
#pragma unroll
                for (int ns = 0; ns < 2; ns++) {
                    const float* wp = Wd2 + (k0 + 8 + kr) * 128 + n0 + ns * 8 + gr;
                    bn[ns][0] = f2tf(wp[0]);
                    bn[ns][1] = f2tf(wp[512]);
                }
            }
#pragma unroll
            for (int mt = 0; mt < 6; mt++) {
                const float* ap = t1S + (mt * 16 + gr) * P + k0 + kr;
                uint32_t a0 = __float_as_uint(ap[0]);
                uint32_t a1 = __float_as_uint(ap[8 * P]);
                uint32_t a2 = __float_as_uint(ap[4]);
                uint32_t a3 = __float_as_uint(ap[8 * P + 4]);
#pragma unroll
                for (int ns = 0; ns < 2; ns++)
                    mma8(acc[mt][ns], a0, a1, a2, a3, bc[ns][0], bc[ns][1]);
            }
#pragma unroll
            for (int ns = 0; ns < 2; ns++) {
                bc[ns][0] = bn[ns][0];
                bc[ns][1] = bn[ns][1];
            }
        }
#pragma unroll
        for (int ns = 0; ns < 2; ns++) {
            int cb = n0 + ns * 8 + 2 * kr;
            float bv0 = bd2[cb], bv1 = bd2[cb + 1];
#pragma unroll
            for (int mt = 0; mt < 6; mt++) {
                int r0 = mt * 16 + gr;
                size_t idx0 = ((size_t)bi * N + r0) * HID + cb;
                float2 m0 = *(float2*)&g_mask[idx0];
                m0.x *= silu_f(acc[mt][ns][0] + bv0);
                m0.y *= silu_f(acc[mt][ns][1] + bv1);
                *(float2*)&g_mask[idx0] = m0;
                size_t idx1 = ((size_t)bi * N + r0 + 8) * HID + cb;
                float2 m1 = *(float2*)&g_mask[idx1];
                m1.x *= silu_f(acc[mt][ns][2] + bv0);
                m1.y *= silu_f(acc[mt][ns][3] + bv1);
                *(float2*)&g_mask[idx1] = m1;
            }
        }
    }
}

// ---------------- K6: s += sum_j mask_ij * s1_j ----------------
__global__ void k_agg() {
    int i = blockIdx.x, b = blockIdx.y, h = threadIdx.x;
    int bi = b * N + i;
    float acc = g_s[bi * HID + h];
    const float* mrow = &g_mask[(size_t)bi * N * HID + h];
#pragma unroll 4
    for (int j = 0; j < N; j++) acc = fmaf(mrow[(size_t)j * HID], g_s1[(b * N + j) * HID + h], acc);
    g_s[bi * HID + h] = acc;
}

// ---------------- K7: readout ----------------
__global__ void k_read(const int* __restrict__ z, const float* __restrict__ Wout,
                       const float* __restrict__ bout, float* __restrict__ out) {
    int b = blockIdx.x;
    int h = threadIdx.x;
    __shared__ float red[4];
    float acc = 0.0f;
    for (int i = 0; i < N; i++) {
        if (z[b * N + i] != 0) acc += g_s[(b * N + i) * HID + h];
    }
    float p = acc * Wout[h];
    float s = blksum128(p, red);
    if (h == 0) out[b] = s + bout[0];
}

// ---------------- launch ----------------
extern "C" void kernel_launch(void* const* d_in, const int* in_sizes, int n_in,
                              void* d_out, int out_size) {
    const int* z = (const int*)d_in[0];
    const float* pos = (const float*)d_in[1];
    const float* emb = (const float*)d_in[2];
    const float* Wef = (const float*)d_in[3];
    const float* bef = (const float*)d_in[4];
    const float* Ws2v = (const float*)d_in[5];
    const float* bs2v = (const float*)d_in[6];
    const float* Wq = (const float*)d_in[7];
    const float* Wk = (const float*)d_in[8];
    const float* Wd1 = (const float*)d_in[9];
    const float* bd1 = (const float*)d_in[10];
    const float* Wd2 = (const float*)d_in[11];
    const float* bd2 = (const float*)d_in[12];
    const float* Wint = (const float*)d_in[13];
    const float* bint = (const float*)d_in[14];
    const float* Wout = (const float*)d_in[15];
    const float* bout = (const float*)d_in[16];
    float* out = (float*)d_out;

    cudaFuncSetAttribute(k_dir, cudaFuncAttributeMaxDynamicSharedMemorySize, SMEM_DIR_BYTES);
    cudaFuncSetAttribute(k_lin8, cudaFuncAttributeMaxDynamicSharedMemorySize, SMEM_LIN_BYTES);
    cudaFuncSetAttribute(k_qk8, cudaFuncAttributeMaxDynamicSharedMemorySize, SMEM_QK_BYTES);

    dim3 g(N, B);
    k_s0<<<BN, 128>>>(z, emb);
    k_geomne<<<g, 128>>>(z, pos, Wef, bef);
    k_lin8<<<BN / LIN_R, 128, SMEM_LIN_BYTES>>>(Ws2v, bs2v);  // -> g_s1
    k_v<<<g, 128>>>();
    k_qk8<<<BN / LIN_R, 128, SMEM_QK_BYTES>>>(Wq, Wk);
    k_dir<<<g, 256, SMEM_DIR_BYTES>>>(Wd1, bd1, Wd2, bd2);
    for (int l = 0; l < L; l++) {
        k_lin8<<<BN / LIN_R, 128, SMEM_LIN_BYTES>>>(Wint + (size_t)l * HID * HID,
                                                    bint + (size_t)l * HID);
        k_agg<<<g, 128>>>();
    }
    k_read<<<B, 128>>>(z, Wout, bout, out);
}

// round 3
// speedup vs baseline: 2.2791x; 1.4018x over previous
#include <cuda_runtime.h>
#include <cuda_bf16.h>
#include <cstdint>
#include <cstddef>

#define DEVFN __device__ __forceinline__

constexpr int B = 16, N = 96, HID = 128, EF = 32, L = 4;
constexpr int BN = B * N;
constexpr float CUTOFF = 10.0f, RBF_GAMMA = 10.0f;
constexpr float PI_F = 3.14159265358979323846f;

// ---------------- scratch (device globals) ----------------
__device__ float g_mask[(size_t)BN * N * HID];  // 75.5 MB
__device__ float g_s0[BN * HID];
__device__ float g_s[BN * HID];
__device__ float g_s1[BN * HID];
__device__ float g_v[BN * 3 * HID];
__device__ float g_qv[BN * 3 * HID];
__device__ float g_kv[BN * 3 * HID];
__device__ float g_ea[BN * N];
__device__ float g_ev[BN * N * 3];
__device__ uint32_t g_W1p[128 * 256];  // Wd1 packed bf16x2 (k-pairs)
__device__ uint32_t g_W2p[128 * 128];  // Wd2 packed bf16x2

DEVFN float silu_f(float x) { return x / (1.0f + __expf(-x)); }

DEVFN void fma4(float4& a, float x, const float4 w) {
    a.x = fmaf(x, w.x, a.x);
    a.y = fmaf(x, w.y, a.y);
    a.z = fmaf(x, w.z, a.z);
    a.w = fmaf(x, w.w, a.w);
}
DEVFN void fma44(float4& a, const float4 x, const float4 w) {
    a.x = fmaf(x.x, w.x, a.x);
    a.y = fmaf(x.y, w.y, a.y);
    a.z = fmaf(x.z, w.z, a.z);
    a.w = fmaf(x.w, w.w, a.w);
}

DEVFN uint32_t packbf(float lo, float hi) {
    uint32_t r;
    asm("cvt.rn.bf16x2.f32 %0, %1, %2;" : "=r"(r) : "f"(hi), "f"(lo));
    return r;
}

DEVFN void mma16(float c[4], uint32_t a0, uint32_t a1, uint32_t a2, uint32_t a3,
                 uint32_t b0, uint32_t b1) {
    asm volatile(
        "mma.sync.aligned.m16n8k16.row.col.f32.bf16.bf16.f32 "
        "{%0,%1,%2,%3},{%4,%5,%6,%7},{%8,%9},{%0,%1,%2,%3};\n"
        : "+f"(c[0]), "+f"(c[1]), "+f"(c[2]), "+f"(c[3])
        : "r"(a0), "r"(a1), "r"(a2), "r"(a3), "r"(b0), "r"(b1));
}

DEVFN float blksum128(float v, float* red) {
#pragma unroll
    for (int o = 16; o; o >>= 1) v += __shfl_xor_sync(0xffffffffu, v, o);
    if ((threadIdx.x & 31) == 0) red[threadIdx.x >> 5] = v;
    __syncthreads();
    float r = red[0] + red[1] + red[2] + red[3];
    __syncthreads();
    return r;
}

// ---------------- K-1: pack Wd1/Wd2 into bf16x2 k-pair layout ----------------
__global__ void k_prep(const float* __restrict__ Wd1, const float* __restrict__ Wd2) {
    int idx = blockIdx.x * 256 + threadIdx.x;
    if (idx < 128 * 256) {
        int kp = idx >> 8, n = idx & 255;
        g_W1p[idx] = packbf(Wd1[(2 * kp) * 256 + n], Wd1[(2 * kp + 1) * 256 + n]);
    } else {
        int r = idx - 128 * 256;
        if (r < 128 * 128) {
            int kp = r >> 7, n = r & 127;
            g_W2p[r] = packbf(Wd2[(2 * kp) * 128 + n], Wd2[(2 * kp + 1) * 128 + n]);
        }
    }
}

// ---------------- K0: s0 = LN(emb_table[z]) ----------------
__global__ void k_s0(const int* __restrict__ z, const float* __restrict__ emb) {
    int bi = blockIdx.x;
    int h = threadIdx.x;
    __shared__ float red[4];
    int zz = z[bi];
    float e = emb[zz * HID + h];
    float m = blksum128(e, red) * (1.0f / HID);
    float dx = e - m;
    float var = blksum128(dx * dx, red) * (1.0f / HID);
    g_s0[bi * HID + h] = dx * rsqrtf(var + 1e-5f);
}

// ---------------- K1: geometry + ef-proj -> mask, fused NeighborEmb ----------------
__global__ void __launch_bounds__(128) k_geomne(const int* __restrict__ z,
                                                const float* __restrict__ pos,
                                                const float* __restrict__ Wef,
                                                const float* __restrict__ bef) {
    int i = blockIdx.x, b = blockIdx.y;
    int bi = b * N + i;
    int t = threadIdx.x, w = t >> 5, lane = t & 31;
    __shared__ float wS[EF * HID];
    __shared__ float bS[HID];
    __shared__ float pS[4][HID];
    for (int k = t; k < EF * HID; k += 128) wS[k] = Wef[k];
    bS[t] = bef[t];
    float padi = (z[bi] != 0) ? 1.0f : 0.0f;
    float xi = pos[bi * 3 + 0];
    float yi = pos[bi * 3 + 1];
    float zi = pos[bi * 3 + 2];
    __syncthreads();
    float4 bb = *(const float4*)&bS[lane * 4];
    float4 sacc = make_float4(0.f, 0.f, 0.f, 0.f);
    for (int j = w; j < N; j += 4) {
        float padj = (z[b * N + j] != 0) ? 1.0f : 0.0f;
        float dx = pos[(b * N + j) * 3 + 0] - xi;
        float dy = pos[(b * N + j) * 3 + 1] - yi;
        float dz = pos[(b * N + j) * 3 + 2] - zi;
        float d = sqrtf(dx * dx + dy * dy + dz * dz + 1e-12f);
        float pm = padi * padj * ((i != j) ? 1.0f : 0.0f);
        float ea = (d < CUTOFF) ? 0.5f * (cosf(PI_F * d * (1.0f / CUTOFF)) + 1.0f) * pm : 0.0f;
        float inv = pm / (d + 1e-12f);
        float cc = lane * (CUTOFF / (EF - 1));
        float dd = d - cc;
        float efv = __expf(-RBF_GAMMA * dd * dd) * pm;
        float4 acc = bb;
#pragma unroll
        for (int k = 0; k < EF; k++) {
            float e = __shfl_sync(0xffffffffu, efv, k);
            float4 w4 = *(const float4*)&wS[k * HID + lane * 4];
            fma4(acc, e, w4);
        }
        float4 mv;
        mv.x = silu_f(acc.x) * ea;
        mv.y = silu_f(acc.y) * ea;
        mv.z = silu_f(acc.z) * ea;
        mv.w = silu_f(acc.w) * ea;
        *(float4*)&g_mask[((size_t)bi * N + j) * HID + lane * 4] = mv;
        float4 s0j = *(const float4*)&g_s0[(b * N + j) * HID + lane * 4];
        fma44(sacc, mv, s0j);
        if (lane == 0) {
            size_t pidx = (size_t)bi * N + j;
            g_ea[pidx] = ea;
            g_ev[pidx * 3 + 0] = dx * inv;
            g_ev[pidx * 3 + 1] = dy * inv;
            g_ev[pidx * 3 + 2] = dz * inv;
        }
    }
    *(float4*)&pS[w][lane * 4] = sacc;
    __syncthreads();
    float s = g_s0[bi * HID + t] + pS[0][t] + pS[1][t] + pS[2][t] + pS[3][t];
    g_s[bi * HID + t] = s;
}

// ---------------- K2: batched  s1 = silu(LN(s @ W + b)), 8 atoms/block ----------------
constexpr int LIN_R = 8;
constexpr int SMEM_LIN_BYTES = (HID * HID + 2 * LIN_R * HID + 16) * 4;
__global__ void __launch_bounds__(128) k_lin8(const float* __restrict__ W,
                                              const float* __restrict__ bv) {
    extern __shared__ float sm[];
    float* wS = sm;
    float* sS = wS + HID * HID;
    float* oS = sS + LIN_R * HID;
    float* mS = oS + LIN_R * HID;
    float* vS = mS + 8;
    int t = threadIdx.x, w = t >> 5, lane = t & 31;
    int base = blockIdx.x * LIN_R;
    for (int k = t; k < HID * HID; k += 128) wS[k] = W[k];
    for (int k = t; k < LIN_R * HID; k += 128) sS[k] = g_s[base * HID + k];
    __syncthreads();
    float acc[LIN_R];
    float bb = bv[t];
#pragma unroll
    for (int r = 0; r < LIN_R; r++) acc[r] = bb;
#pragma unroll 4
    for (int h = 0; h < HID; h++) {
        float wv = wS[h * HID + t];
#pragma unroll
        for (int r = 0; r < LIN_R; r++) acc[r] = fmaf(sS[r * HID + h], wv, acc[r]);
    }
#pragma unroll
    for (int r = 0; r < LIN_R; r++) oS[r * HID + t] = acc[r];
    __syncthreads();
    for (int r = w; r < LIN_R; r += 4) {
        float x0 = oS[r * HID + lane], x1 = oS[r * HID + lane + 32];
        float x2 = oS[r * HID + lane + 64], x3 = oS[r * HID + lane + 96];
        float s = x0 + x1 + x2 + x3;
#pragma unroll
        for (int o = 16; o; o >>= 1) s += __shfl_xor_sync(0xffffffffu, s, o);
        float mean = s * (1.0f / HID);
        float q0 = x0 - mean, q1 = x1 - mean, q2 = x2 - mean, q3 = x3 - mean;
        float q = q0 * q0 + q1 * q1 + q2 * q2 + q3 * q3;
#pragma unroll
        for (int o = 16; o; o >>= 1) q += __shfl_xor_sync(0xffffffffu, q, o);
        if (lane == 0) {
            mS[r] = mean;
            vS[r] = rsqrtf(q * (1.0f / HID) + 1e-5f);
        }
    }
    __syncthreads();
#pragma unroll
    for (int r = 0; r < LIN_R; r++) {
        float val = (oS[r * HID + t] - mS[r]) * vS[r];
        g_s1[(base + r) * HID + t] = silu_f(val);
    }
}

// ---------------- K3: v_i = sum_j mask_ij * s1_j * ev_ij (float4, 4 rows in flight) ----
__global__ void __launch_bounds__(128) k_v() {
    int i = blockIdx.x, b = blockIdx.y;
    int bi = b * N + i;
    int t = threadIdx.x, c = t & 31, jr = t >> 5;
    __shared__ float4 red[3][4][32];
    float4 a0 = make_float4(0.f, 0.f, 0.f, 0.f), a1 = a0, a2 = a0;
    const float* mrow = &g_mask[(size_t)bi * N * HID + c * 4];
    const float* evrow = &g_ev[(size_t)bi * N * 3];
#pragma unroll 6
    for (int j = jr; j < N; j += 4) {
        float4 m4 = *(const float4*)&mrow[(size_t)j * HID];
        float4 s4 = *(const float4*)&g_s1[(b * N + j) * HID + c * 4];
        float e0 = evrow[j * 3 + 0], e1 = evrow[j * 3 + 1], e2 = evrow[j * 3 + 2];
        float4 wv;
        wv.x = m4.x * s4.x;
        wv.y = m4.y * s4.y;
        wv.z = m4.z * s4.z;
        wv.w = m4.w * s4.w;
        fma4(a0, e0, wv);
        fma4(a1, e1, wv);
        fma4(a2, e2, wv);
    }
    red[0][jr][c] = a0;
    red[1][jr][c] = a1;
    red[2][jr][c] = a2;
    __syncthreads();
    if (jr < 3) {
        float4 r0 = red[jr][0][c], r1 = red[jr][1][c], r2 = red[jr][2][c], r3 = red[jr][3][c];
        float4 s;
        s.x = r0.x + r1.x + r2.x + r3.x;
        s.y = r0.y + r1.y + r2.y + r3.y;
        s.z = r0.z + r1.z + r2.z + r3.z;
        s.w = r0.w + r1.w + r2.w + r3.w;
        *(float4*)&g_v[(bi * 3 + jr) * HID + c * 4] = s;
    }
}

// ---------------- K4: batched qv/kv, 8 atoms/block ----------------
constexpr int SMEM_QK_BYTES = (2 * HID * HID + LIN_R * 3 * HID) * 4;
__global__ void __launch_bounds__(128) k_qk8(const float* __restrict__ Wq,
                                             const float* __restrict__ Wk) {
    extern __shared__ float sm[];
    float* wqS = sm;
    float* wkS = wqS + HID * HID;
    float* vS = wkS + HID * HID;
    int t = threadIdx.x;
    int base = blockIdx.x * LIN_R;
    for (int k = t; k < HID * HID; k += 128) {
        wqS[k] = Wq[k];
        wkS[k] = Wk[k];
    }
    for (int k = t; k < LIN_R * 3 * HID; k += 128) vS[k] = g_v[base * 3 * HID + k];
    __syncthreads();
#pragma unroll
    for (int k3 = 0; k3 < 3; k3++) {
        float aq[LIN_R], ak[LIN_R];
#pragma unroll
        for (int r = 0; r < LIN_R; r++) { aq[r] = 0.f; ak[r] = 0.f; }
#pragma unroll 4
        for (int h = 0; h < HID; h++) {
            float wq = wqS[h * HID + t];
            float wk = wkS[h * HID + t];
#pragma unroll
            for (int r = 0; r < LIN_R; r++) {
                float vv = vS[r * 3 * HID + k3 * HID + h];
                aq[r] = fmaf(vv, wq, aq[r]);
                ak[r] = fmaf(vv, wk, ak[r]);
            }
        }
#pragma unroll
        for (int r = 0; r < LIN_R; r++) {
            g_qv[((base + r) * 3 + k3) * HID + t] = aq[r];
            g_kv[((base + r) * 3 + k3) * HID + t] = ak[r];
        }
    }
}

// ---------------- K5: fused directional MLP, bf16 mma: mask *= dp ----------------
constexpr int PW = 132;  // smem pitch in b32 words (bf16x2 pairs); 132 % 32 = 4
constexpr int SMEM_DIR_WORDS = 2 * N * PW + 2 * 3 * HID + N + 3 * N;
constexpr int SMEM_DIR_BYTES = SMEM_DIR_WORDS * 4;  // ~106 KB

__global__ void __launch_bounds__(512, 1) k_dir(const float* __restrict__ bd1,
                                                const float* __restrict__ bd2) {
    int i = blockIdx.x, b = blockIdx.y;
    int bi = b * N + i;
    int t = threadIdx.x, w = t >> 5, lane = t & 31;
    int gr = lane >> 2, kr = lane & 3;
    int wm = w >> 3, wn = w & 7;  // wm: 0..1 (48-row halves), wn: 0..7
    extern __shared__ float sm[];
    uint32_t* dirfS = (uint32_t*)sm;      // 96 x PW bf16x2
    uint32_t* t1S = dirfS + N * PW;       // 96 x PW bf16x2
    float* vS = (float*)(t1S + N * PW);
    float* kvS = vS + 3 * HID;
    float* eaS = kvS + 3 * HID;
    float* evS = eaS + N;

    for (int k = t; k < 3 * HID; k += 512) {
        vS[k] = g_v[bi * 3 * HID + k];
        kvS[k] = g_kv[bi * 3 * HID + k];
    }
    if (t < N) eaS[t] = g_ea[(size_t)bi * N + t];
    if (t < 3 * N) evS[t] = g_ev[(size_t)bi * N * 3 + t];
    __syncthreads();

    // dirf = concat(dir2, dir3) * ea, packed bf16x2 (h pairs)
    for (int e = t; e < N * 64; e += 512) {
        int j = e >> 6, hp = e & 63;
        int h = hp * 2;
        float e0 = evS[j * 3 + 0], e1 = evS[j * 3 + 1], e2 = evS[j * 3 + 2];
        float ea = eaS[j];
        float d2a = (vS[h] * e0 + vS[HID + h] * e1 + vS[2 * HID + h] * e2) * ea;
        float d2b = (vS[h + 1] * e0 + vS[HID + h + 1] * e1 + vS[2 * HID + h + 1] * e2) * ea;
        const float* qj = &g_qv[(size_t)(b * N + j) * 3 * HID + h];
        float d3a = (qj[0] * kvS[h] + qj[HID] * kvS[HID + h] + qj[2 * HID] * kvS[2 * HID + h]) * ea;
        float d3b = (qj[1] * kvS[h + 1] + qj[HID + 1] * kvS[HID + h + 1] +
                     qj[2 * HID + 1] * kvS[2 * HID + h + 1]) * ea;
        dirfS[j * PW + hp] = packbf(d2a, d2b);
        dirfS[j * PW + 64 + hp] = packbf(d3a, d3b);
    }
    __syncthreads();

    // phase 3: t1 = silu(dirf(96x256) @ Wd1 + bd1); warp (wm,wn): rows wm*48+, cols wn*32+
    {
        int n0 = wn * 32;
        float acc[3][4][4];
#pragma unroll
        for (int mt = 0; mt < 3; mt++)
#pragma unroll
            for (int ns = 0; ns < 4; ns++)
#pragma unroll
                for (int c = 0; c < 4; c++) acc[mt][ns][c] = 0.f;
        uint32_t bc[4][2], bn[4][2];
#pragma unroll
        for (int ns = 0; ns < 4; ns++) {
            bc[ns][0] = g_W1p[(kr) * 256 + n0 + ns * 8 + gr];
            bc[ns][1] = g_W1p[(kr + 4) * 256 + n0 + ns * 8 + gr];
        }
        for (int ks = 0; ks < 16; ks++) {
            int kp0 = ks * 8;
            if (ks < 15) {
#pragma unroll
                for (int ns = 0; ns < 4; ns++) {
                    bn[ns][0] = g_W1p[(kp0 + 8 + kr) * 256 + n0 + ns * 8 + gr];
                    bn[ns][1] = g_W1p[(kp0 + 12 + kr) * 256 + n0 + ns * 8 + gr];
                }
            }
#pragma unroll
            for (int mt = 0; mt < 3; mt++) {
                int row = wm * 48 + mt * 16 + gr;
                uint32_t a0 = dirfS[row * PW + kp0 + kr];
                uint32_t a1 = dirfS[(row + 8) * PW + kp0 + kr];
                uint32_t a2 = dirfS[row * PW + kp0 + kr + 4];
                uint32_t a3 = dirfS[(row + 8) * PW + kp0 + kr + 4];
#pragma unroll
                for (int ns = 0; ns < 4; ns++)
                    mma16(acc[mt][ns], a0, a1, a2, a3, bc[ns][0], bc[ns][1]);
            }
#pragma unroll
            for (int ns = 0; ns < 4; ns++) {
                bc[ns][0] = bn[ns][0];
                bc[ns][1] = bn[ns][1];
            }
        }
#pragma unroll
        for (int ns = 0; ns < 4; ns++) {
            int col0 = n0 + ns * 8 + 2 * kr;
            float bv0 = bd1[col0], bv1 = bd1[col0 + 1];
            int wp = (col0 >> 1);
#pragma unroll
            for (int mt = 0; mt < 3; mt++) {
                int row = wm * 48 + mt * 16 + gr;
                t1S[row * PW + wp] = packbf(silu_f(acc[mt][ns][0] + bv0), silu_f(acc[mt][ns][1] + bv1));
                t1S[(row + 8) * PW + wp] = packbf(silu_f(acc[mt][ns][2] + bv0), silu_f(acc[mt][ns][3] + bv1));
            }
        }
    }
    __syncthreads();

    // phase 4: dp = silu(t1(96x256) @ Wd2 + bd2); mask *= dp; warp cols wn*16+
    {
        int n0 = wn * 16;
        float acc[3][2][4];
#pragma unroll
        for (int mt = 0; mt < 3; mt++)
#pragma unroll
            for (int ns = 0; ns < 2; ns++)
#pragma unroll
                for (int c = 0; c < 4; c++) acc[mt][ns][c] = 0.f;
        uint32_t bc[2][2], bn[2][2];
#pragma unroll
        for (int ns = 0; ns < 2; ns++) {
            bc[ns][0] = g_W2p[(kr) * 128 + n0 + ns * 8 + gr];
            bc[ns][1] = g_W2p[(kr + 4) * 128 + n0 + ns * 8 + gr];
        }
        for (int ks = 0; ks < 16; ks++) {
            int kp0 = ks * 8;
            if (ks < 15) {
#pragma unroll
                for (int ns = 0; ns < 2; ns++) {
                    bn[ns][0] = g_W2p[(kp0 + 8 + kr) * 128 + n0 + ns * 8 + gr];
                    bn[ns][1] = g_W2p[(kp0 + 12 + kr) * 128 + n0 + ns * 8 + gr];
                }
            }
#pragma unroll
            for (int mt = 0; mt < 3; mt++) {
                int row = wm * 48 + mt * 16 + gr;
                uint32_t a0 = t1S[row * PW + kp0 + kr];
                uint32_t a1 = t1S[(row + 8) * PW + kp0 + kr];
                uint32_t a2 = t1S[row * PW + kp0 + kr + 4];
                uint32_t a3 = t1S[(row + 8) * PW + kp0 + kr + 4];
#pragma unroll
                for (int ns = 0; ns < 2; ns++)
                    mma16(acc[mt][ns], a0, a1, a2, a3, bc[ns][0], bc[ns][1]);
            }
#pragma unroll
            for (int ns = 0; ns < 2; ns++) {
                bc[ns][0] = bn[ns][0];
                bc[ns][1] = bn[ns][1];
            }
        }
#pragma unroll
        for (int ns = 0; ns < 2; ns++) {
            int col0 = n0 + ns * 8 + 2 * kr;
            float bv0 = bd2[col0], bv1 = bd2[col0 + 1];
#pragma unroll
            for (int mt = 0; mt < 3; mt++) {
                int row = wm * 48 + mt * 16 + gr;
                size_t idx0 = ((size_t)bi * N + row) * HID + col0;
                float2 m0 = *(float2*)&g_mask[idx0];
                m0.x *= silu_f(acc[mt][ns][0] + bv0);
                m0.y *= silu_f(acc[mt][ns][1] + bv1);
                *(float2*)&g_mask[idx0] = m0;
                size_t idx1 = ((size_t)bi * N + row + 8) * HID + col0;
                float2 m1 = *(float2*)&g_mask[idx1];
                m1.x *= silu_f(acc[mt][ns][2] + bv0);
                m1.y *= silu_f(acc[mt][ns][3] + bv1);
                *(float2*)&g_mask[idx1] = m1;
            }
        }
    }
}

// ---------------- K6: s += sum_j mask_ij * s1_j (float4, 4 rows in flight) ----------------
__global__ void __launch_bounds__(128) k_agg() {
    int i = blockIdx.x, b = blockIdx.y;
    int bi = b * N + i;
    int t = threadIdx.x, c = t & 31, jr = t >> 5;
    __shared__ float4 red[4][32];
    float4 acc = make_float4(0.f, 0.f, 0.f, 0.f);
    const float* mrow = &g_mask[(size_t)bi * N * HID + c * 4];
#pragma unroll 6
    for (int j = jr; j < N; j += 4) {
        float4 m4 = *(const float4*)&mrow[(size_t)j * HID];
        float4 s4 = *(const float4*)&g_s1[(b * N + j) * HID + c * 4];
        fma44(acc, m4, s4);
    }
    red[jr][c] = acc;
    __syncthreads();
    if (jr == 0) {
        float4 r0 = red[0][c], r1 = red[1][c], r2 = red[2][c], r3 = red[3][c];
        float4 s = *(const float4*)&g_s[bi * HID + c * 4];
        s.x += r0.x + r1.x + r2.x + r3.x;
        s.y += r0.y + r1.y + r2.y + r3.y;
        s.z += r0.z + r1.z + r2.z + r3.z;
        s.w += r0.w + r1.w + r2.w + r3.w;
        *(float4*)&g_s[bi * HID + c * 4] = s;
    }
}

// ---------------- K7: readout ----------------
__global__ void k_read(const int* __restrict__ z, const float* __restrict__ Wout,
                       const float* __restrict__ bout, float* __restrict__ out) {
    int b = blockIdx.x;
    int h = threadIdx.x;
    __shared__ float red[4];
    float acc = 0.0f;
    for (int i = 0; i < N; i++) {
        if (z[b * N + i] != 0) acc += g_s[(b * N + i) * HID + h];
    }
    float p = acc * Wout[h];
    float s = blksum128(p, red);
    if (h == 0) out[b] = s + bout[0];
}

// ---------------- launch ----------------
extern "C" void kernel_launch(void* const* d_in, const int* in_sizes, int n_in,
                              void* d_out, int out_size) {
    const int* z = (const int*)d_in[0];
    const float* pos = (const float*)d_in[1];
    const float* emb = (const float*)d_in[2];
    const float* Wef = (const float*)d_in[3];
    const float* bef = (const float*)d_in[4];
    const float* Ws2v = (const float*)d_in[5];
    const float* bs2v = (const float*)d_in[6];
    const float* Wq = (const float*)d_in[7];
    const float* Wk = (const float*)d_in[8];
    const float* Wd1 = (const float*)d_in[9];
    const float* bd1 = (const float*)d_in[10];
    const float* Wd2 = (const float*)d_in[11];
    const float* bd2 = (const float*)d_in[12];
    const float* Wint = (const float*)d_in[13];
    const float* bint = (const float*)d_in[14];
    const float* Wout = (const float*)d_in[15];
    const float* bout = (const float*)d_in[16];
    float* out = (float*)d_out;

    cudaFuncSetAttribute(k_dir, cudaFuncAttributeMaxDynamicSharedMemorySize, SMEM_DIR_BYTES);
    cudaFuncSetAttribute(k_lin8, cudaFuncAttributeMaxDynamicSharedMemorySize, SMEM_LIN_BYTES);
    cudaFuncSetAttribute(k_qk8, cudaFuncAttributeMaxDynamicSharedMemorySize, SMEM_QK_BYTES);

    dim3 g(N, B);
    k_prep<<<(128 * 256 + 128 * 128 + 255) / 256, 256>>>(Wd1, Wd2);
    k_s0<<<BN, 128>>>(z, emb);
    k_geomne<<<g, 128>>>(z, pos, Wef, bef);
    k_lin8<<<BN / LIN_R, 128, SMEM_LIN_BYTES>>>(Ws2v, bs2v);  // -> g_s1
    k_v<<<g, 128>>>();
    k_qk8<<<BN / LIN_R, 128, SMEM_QK_BYTES>>>(Wq, Wk);
    k_dir<<<g, 512, SMEM_DIR_BYTES>>>(bd1, bd2);
    for (int l = 0; l < L; l++) {
        k_lin8<<<BN / LIN_R, 128, SMEM_LIN_BYTES>>>(Wint + (size_t)l * HID * HID,
                                                    bint + (size_t)l * HID);
        k_agg<<<g, 128>>>();
    }
    k_read<<<B, 128>>>(z, Wout, bout, out);
}

// round 4
// speedup vs baseline: 2.7412x; 1.2027x over previous
#include <cuda_runtime.h>
#include <cuda_bf16.h>
#include <cstdint>
#include <cstddef>

#define DEVFN __device__ __forceinline__

constexpr int B = 16, N = 96, HID = 128, EF = 32, L = 4;
constexpr int BN = B * N;
constexpr float CUTOFF = 10.0f, RBF_GAMMA = 10.0f;
constexpr float PI_F = 3.14159265358979323846f;

// ---------------- scratch (device globals) ----------------
__device__ uint32_t g_maskh[(size_t)BN * N * (HID / 2)];  // bf16x2 mask, 37.7 MB
__device__ float g_s0[BN * HID];
__device__ float g_s[BN * HID];
__device__ float g_s1[BN * HID];
__device__ float g_v[BN * 3 * HID];
__device__ float g_qv[BN * 3 * HID];
__device__ float g_kv[BN * 3 * HID];
__device__ float g_ea[BN * N];
__device__ float g_ev[BN * N * 3];
__device__ uint32_t g_W1p[128 * 256];  // Wd1 packed bf16x2 (k-pairs)
__device__ uint32_t g_W2p[128 * 128];  // Wd2 packed bf16x2

DEVFN float silu_f(float x) { return x / (1.0f + __expf(-x)); }

DEVFN void fma4(float4& a, float x, const float4 w) {
    a.x = fmaf(x, w.x, a.x);
    a.y = fmaf(x, w.y, a.y);
    a.z = fmaf(x, w.z, a.z);
    a.w = fmaf(x, w.w, a.w);
}

DEVFN uint32_t packbf(float lo, float hi) {
    uint32_t r;
    asm("cvt.rn.bf16x2.f32 %0, %1, %2;" : "=r"(r) : "f"(hi), "f"(lo));
    return r;
}
DEVFN float2 unpackbf(uint32_t u) {
    __nv_bfloat162 b = *reinterpret_cast<__nv_bfloat162*>(&u);
    return __bfloat1622float2(b);
}

DEVFN void mma16(float c[4], uint32_t a0, uint32_t a1, uint32_t a2, uint32_t a3,
                 uint32_t b0, uint32_t b1) {
    asm volatile(
        "mma.sync.aligned.m16n8k16.row.col.f32.bf16.bf16.f32 "
        "{%0,%1,%2,%3},{%4,%5,%6,%7},{%8,%9},{%0,%1,%2,%3};\n"
        : "+f"(c[0]), "+f"(c[1]), "+f"(c[2]), "+f"(c[3])
        : "r"(a0), "r"(a1), "r"(a2), "r"(a3), "r"(b0), "r"(b1));
}

DEVFN float blksum128(float v, float* red) {
#pragma unroll
    for (int o = 16; o; o >>= 1) v += __shfl_xor_sync(0xffffffffu, v, o);
    if ((threadIdx.x & 31) == 0) red[threadIdx.x >> 5] = v;
    __syncthreads();
    float r = red[0] + red[1] + red[2] + red[3];
    __syncthreads();
    return r;
}

// ---------------- K-1: pack Wd1/Wd2 into bf16x2 k-pair layout ----------------
__global__ void k_prep(const float* __restrict__ Wd1, const float* __restrict__ Wd2) {
    int idx = blockIdx.x * 256 + threadIdx.x;
    if (idx < 128 * 256) {
        int kp = idx >> 8, n = idx & 255;
        g_W1p[idx] = packbf(Wd1[(2 * kp) * 256 + n], Wd1[(2 * kp + 1) * 256 + n]);
    } else {
        int r = idx - 128 * 256;
        if (r < 128 * 128) {
            int kp = r >> 7, n = r & 127;
            g_W2p[r] = packbf(Wd2[(2 * kp) * 128 + n], Wd2[(2 * kp + 1) * 128 + n]);
        }
    }
}

// ---------------- K0: s0 = LN(emb_table[z]) ----------------
__global__ void k_s0(const int* __restrict__ z, const float* __restrict__ emb) {
    int bi = blockIdx.x;
    int h = threadIdx.x;
    __shared__ float red[4];
    int zz = z[bi];
    float e = emb[zz * HID + h];
    float m = blksum128(e, red) * (1.0f / HID);
    float dx = e - m;
    float var = blksum128(dx * dx, red) * (1.0f / HID);
    g_s0[bi * HID + h] = dx * rsqrtf(var + 1e-5f);
}

// ---------------- K1: geometry + ef-proj -> mask(bf16), fused NeighborEmb ----------------
__global__ void __launch_bounds__(128) k_geomne(const int* __restrict__ z,
                                                const float* __restrict__ pos,
                                                const float* __restrict__ Wef,
                                                const float* __restrict__ bef) {
    int i = blockIdx.x, b = blockIdx.y;
    int bi = b * N + i;
    int t = threadIdx.x, w = t >> 5, lane = t & 31;
    __shared__ float wS[EF * HID];
    __shared__ float bS[HID];
    __shared__ float pS[4][HID];
    for (int k = t; k < EF * HID; k += 128) wS[k] = Wef[k];
    bS[t] = bef[t];
    float padi = (z[bi] != 0) ? 1.0f : 0.0f;
    float xi = pos[bi * 3 + 0];
    float yi = pos[bi * 3 + 1];
    float zi = pos[bi * 3 + 2];
    __syncthreads();
    float4 bb = *(const float4*)&bS[lane * 4];
    float4 sacc = make_float4(0.f, 0.f, 0.f, 0.f);
    for (int j = w; j < N; j += 4) {
        float padj = (z[b * N + j] != 0) ? 1.0f : 0.0f;
        float dx = pos[(b * N + j) * 3 + 0] - xi;
        float dy = pos[(b * N + j) * 3 + 1] - yi;
        float dz = pos[(b * N + j) * 3 + 2] - zi;
        float d = sqrtf(dx * dx + dy * dy + dz * dz + 1e-12f);
        float pm = padi * padj * ((i != j) ? 1.0f : 0.0f);
        float ea = (d < CUTOFF) ? 0.5f * (cosf(PI_F * d * (1.0f / CUTOFF)) + 1.0f) * pm : 0.0f;
        float inv = pm / (d + 1e-12f);
        float cc = lane * (CUTOFF / (EF - 1));
        float dd = d - cc;
        float efv = __expf(-RBF_GAMMA * dd * dd) * pm;
        float4 acc = bb;
#pragma unroll
        for (int k = 0; k < EF; k++) {
            float e = __shfl_sync(0xffffffffu, efv, k);
            float4 w4 = *(const float4*)&wS[k * HID + lane * 4];
            fma4(acc, e, w4);
        }
        float4 mv;
        mv.x = silu_f(acc.x) * ea;
        mv.y = silu_f(acc.y) * ea;
        mv.z = silu_f(acc.z) * ea;
        mv.w = silu_f(acc.w) * ea;
        uint2 mp;
        mp.x = packbf(mv.x, mv.y);
        mp.y = packbf(mv.z, mv.w);
        *(uint2*)&g_maskh[((size_t)bi * N + j) * (HID / 2) + lane * 2] = mp;
        // use the bf16-rounded mask for the aggregation so downstream matches
        float2 ma = unpackbf(mp.x), mb = unpackbf(mp.y);
        float4 s0j = *(const float4*)&g_s0[(b * N + j) * HID + lane * 4];
        sacc.x = fmaf(ma.x, s0j.x, sacc.x);
        sacc.y = fmaf(ma.y, s0j.y, sacc.y);
        sacc.z = fmaf(mb.x, s0j.z, sacc.z);
        sacc.w = fmaf(mb.y, s0j.w, sacc.w);
        if (lane == 0) {
            size_t pidx = (size_t)bi * N + j;
            g_ea[pidx] = ea;
            g_ev[pidx * 3 + 0] = dx * inv;
            g_ev[pidx * 3 + 1] = dy * inv;
            g_ev[pidx * 3 + 2] = dz * inv;
        }
    }
    *(float4*)&pS[w][lane * 4] = sacc;
    __syncthreads();
    float s = g_s0[bi * HID + t] + pS[0][t] + pS[1][t] + pS[2][t] + pS[3][t];
    g_s[bi * HID + t] = s;
}

// ---------------- K2: s1 = silu(LN(s @ W + b)), 4 atoms/block, no weight staging ----------
constexpr int LIN_R = 4;
__global__ void __launch_bounds__(128) k_lin4(const float* __restrict__ W,
                                              const float* __restrict__ bv) {
    __shared__ float sS[LIN_R][HID];
    __shared__ float oS[LIN_R][HID];
    __shared__ float mS[LIN_R], vS[LIN_R];
    int t = threadIdx.x, w = t >> 5, lane = t & 31;
    int base = blockIdx.x * LIN_R;
    for (int k = t; k < LIN_R * HID; k += 128) sS[k >> 7][k & 127] = g_s[base * HID + k];
    __syncthreads();
    float acc0 = 0.f, acc1 = 0.f, acc2 = 0.f, acc3 = 0.f;
#pragma unroll 8
    for (int h = 0; h < HID; h++) {
        float wv = __ldg(&W[h * HID + t]);
        acc0 = fmaf(sS[0][h], wv, acc0);
        acc1 = fmaf(sS[1][h], wv, acc1);
        acc2 = fmaf(sS[2][h], wv, acc2);
        acc3 = fmaf(sS[3][h], wv, acc3);
    }
    float bb = bv[t];
    oS[0][t] = acc0 + bb;
    oS[1][t] = acc1 + bb;
    oS[2][t] = acc2 + bb;
    oS[3][t] = acc3 + bb;
    __syncthreads();
    {
        int r = w;
        float x0 = oS[r][lane], x1 = oS[r][lane + 32], x2 = oS[r][lane + 64], x3 = oS[r][lane + 96];
        float s = x0 + x1 + x2 + x3;
#pragma unroll
        for (int o = 16; o; o >>= 1) s += __shfl_xor_sync(0xffffffffu, s, o);
        float mean = s * (1.0f / HID);
        float q0 = x0 - mean, q1 = x1 - mean, q2 = x2 - mean, q3 = x3 - mean;
        float q = q0 * q0 + q1 * q1 + q2 * q2 + q3 * q3;
#pragma unroll
        for (int o = 16; o; o >>= 1) q += __shfl_xor_sync(0xffffffffu, q, o);
        if (lane == 0) {
            mS[r] = mean;
            vS[r] = rsqrtf(q * (1.0f / HID) + 1e-5f);
        }
    }
    __syncthreads();
#pragma unroll
    for (int r = 0; r < LIN_R; r++) {
        float val = (oS[r][t] - mS[r]) * vS[r];
        g_s1[(base + r) * HID + t] = silu_f(val);
    }
}

// ---------------- K3: v_i = sum_j mask_ij * s1_j * ev_ij ----------------
__global__ void __launch_bounds__(128) k_v() {
    int i = blockIdx.x, b = blockIdx.y;
    int bi = b * N + i;
    int t = threadIdx.x, c = t & 31, jr = t >> 5;
    __shared__ float4 red[3][4][32];
    float4 a0 = make_float4(0.f, 0.f, 0.f, 0.f), a1 = a0, a2 = a0;
    const uint32_t* mrow = &g_maskh[(size_t)bi * N * (HID / 2) + c * 2];
    const float* evrow = &g_ev[(size_t)bi * N * 3];
#pragma unroll 6
    for (int j = jr; j < N; j += 4) {
        uint2 mp = *(const uint2*)&mrow[(size_t)j * (HID / 2)];
        float2 ma = unpackbf(mp.x), mb = unpackbf(mp.y);
        float4 s4 = *(const float4*)&g_s1[(b * N + j) * HID + c * 4];
        float e0 = evrow[j * 3 + 0], e1 = evrow[j * 3 + 1], e2 = evrow[j * 3 + 2];
        float4 wv;
        wv.x = ma.x * s4.x;
        wv.y = ma.y * s4.y;
        wv.z = mb.x * s4.z;
        wv.w = mb.y * s4.w;
        fma4(a0, e0, wv);
        fma4(a1, e1, wv);
        fma4(a2, e2, wv);
    }
    red[0][jr][c] = a0;
    red[1][jr][c] = a1;
    red[2][jr][c] = a2;
    __syncthreads();
    if (jr < 3) {
        float4 r0 = red[jr][0][c], r1 = red[jr][1][c], r2 = red[jr][2][c], r3 = red[jr][3][c];
        float4 s;
        s.x = r0.x + r1.x + r2.x + r3.x;
        s.y = r0.y + r1.y + r2.y + r3.y;
        s.z = r0.z + r1.z + r2.z + r3.z;
        s.w = r0.w + r1.w + r2.w + r3.w;
        *(float4*)&g_v[(bi * 3 + jr) * HID + c * 4] = s;
    }
}

// ---------------- K4: qv/kv, 4 atoms/block, no weight staging ----------------
__global__ void __launch_bounds__(128) k_qk4(const float* __restrict__ Wq,
                                             const float* __restrict__ Wk) {
    __shared__ float vS[LIN_R][3 * HID];
    int t = threadIdx.x;
    int base = blockIdx.x * LIN_R;
    for (int k = t; k < LIN_R * 3 * HID; k += 128) vS[k / (3 * HID)][k % (3 * HID)] = g_v[base * 3 * HID + k];
    __syncthreads();
    float aq[LIN_R][3], ak[LIN_R][3];
#pragma unroll
    for (int r = 0; r < LIN_R; r++)
#pragma unroll
        for (int k3 = 0; k3 < 3; k3++) { aq[r][k3] = 0.f; ak[r][k3] = 0.f; }
#pragma unroll 4
    for (int h = 0; h < HID; h++) {
        float wq = __ldg(&Wq[h * HID + t]);
        float wk = __ldg(&Wk[h * HID + t]);
#pragma unroll
        for (int r = 0; r < LIN_R; r++)
#pragma unroll
            for (int k3 = 0; k3 < 3; k3++) {
                float vv = vS[r][k3 * HID + h];
                aq[r][k3] = fmaf(vv, wq, aq[r][k3]);
                ak[r][k3] = fmaf(vv, wk, ak[r][k3]);
            }
    }
#pragma unroll
    for (int r = 0; r < LIN_R; r++)
#pragma unroll
        for (int k3 = 0; k3 < 3; k3++) {
            g_qv[((base + r) * 3 + k3) * HID + t] = aq[r][k3];
            g_kv[((base + r) * 3 + k3) * HID + t] = ak[r][k3];
        }
}

// ---------------- K5: fused directional MLP, bf16 mma: mask *= dp ----------------
constexpr int PW = 132;  // smem pitch in b32 words (bf16x2 pairs); 132 % 32 = 4
constexpr int SMEM_DIR_WORDS = 2 * N * PW + 2 * 3 * HID + N + 3 * N;
constexpr int SMEM_DIR_BYTES = SMEM_DIR_WORDS * 4;  // ~106 KB

__global__ void __launch_bounds__(512, 1) k_dir(const float* __restrict__ bd1,
                                                const float* __restrict__ bd2) {
    int i = blockIdx.x, b = blockIdx.y;
    int bi = b * N + i;
    int t = threadIdx.x, w = t >> 5, lane = t & 31;
    int gr = lane >> 2, kr = lane & 3;
    int wm = w >> 3, wn = w & 7;  // wm: 0..1 (48-row halves), wn: 0..7
    extern __shared__ float sm[];
    uint32_t* dirfS = (uint32_t*)sm;      // 96 x PW bf16x2
    uint32_t* t1S = dirfS + N * PW;       // 96 x PW bf16x2
    float* vS = (float*)(t1S + N * PW);
    float* kvS = vS + 3 * HID;
    float* eaS = kvS + 3 * HID;
    float* evS = eaS + N;

    for (int k = t; k < 3 * HID; k += 512) {
        vS[k] = g_v[bi * 3 * HID + k];
        kvS[k] = g_kv[bi * 3 * HID + k];
    }
    if (t < N) eaS[t] = g_ea[(size_t)bi * N + t];
    if (t < 3 * N) evS[t] = g_ev[(size_t)bi * N * 3 + t];
    __syncthreads();

    // dirf = concat(dir2, dir3) * ea, packed bf16x2 (h pairs)
    for (int e = t; e < N * 64; e += 512) {
        int j = e >> 6, hp = e & 63;
        int h = hp * 2;
        float e0 = evS[j * 3 + 0], e1 = evS[j * 3 + 1], e2 = evS[j * 3 + 2];
        float ea = eaS[j];
        float d2a = (vS[h] * e0 + vS[HID + h] * e1 + vS[2 * HID + h] * e2) * ea;
        float d2b = (vS[h + 1] * e0 + vS[HID + h + 1] * e1 + vS[2 * HID + h + 1] * e2) * ea;
        const float* qj = &g_qv[(size_t)(b * N + j) * 3 * HID + h];
        float d3a = (qj[0] * kvS[h] + qj[HID] * kvS[HID + h] + qj[2 * HID] * kvS[2 * HID + h]) * ea;
        float d3b = (qj[1] * kvS[h + 1] + qj[HID + 1] * kvS[HID + h + 1] +
                     qj[2 * HID + 1] * kvS[2 * HID + h + 1]) * ea;
        dirfS[j * PW + hp] = packbf(d2a, d2b);
        dirfS[j * PW + 64 + hp] = packbf(d3a, d3b);
    }
    __syncthreads();

    // phase 3: t1 = silu(dirf(96x256) @ Wd1 + bd1)
    {
        int n0 = wn * 32;
        float acc[3][4][4];
#pragma unroll
        for (int mt = 0; mt < 3; mt++)
#pragma unroll
            for (int ns = 0; ns < 4; ns++)
#pragma unroll
                for (int c = 0; c < 4; c++) acc[mt][ns][c] = 0.f;
        uint32_t bc[4][2], bn[4][2];
#pragma unroll
        for (int ns = 0; ns < 4; ns++) {
            bc[ns][0] = g_W1p[(kr) * 256 + n0 + ns * 8 + gr];
            bc[ns][1] = g_W1p[(kr + 4) * 256 + n0 + ns * 8 + gr];
        }
        for (int ks = 0; ks < 16; ks++) {
            int kp0 = ks * 8;
            if (ks < 15) {
#pragma unroll
                for (int ns = 0; ns < 4; ns++) {
                    bn[ns][0] = g_W1p[(kp0 + 8 + kr) * 256 + n0 + ns * 8 + gr];
                    bn[ns][1] = g_W1p[(kp0 + 12 + kr) * 256 + n0 + ns * 8 + gr];
                }
            }
#pragma unroll
            for (int mt = 0; mt < 3; mt++) {
                int row = wm * 48 + mt * 16 + gr;
                uint32_t a0 = dirfS[row * PW + kp0 + kr];
                uint32_t a1 = dirfS[(row + 8) * PW + kp0 + kr];
                uint32_t a2 = dirfS[row * PW + kp0 + kr + 4];
                uint32_t a3 = dirfS[(row + 8) * PW + kp0 + kr + 4];
#pragma unroll
                for (int ns = 0; ns < 4; ns++)
                    mma16(acc[mt][ns], a0, a1, a2, a3, bc[ns][0], bc[ns][1]);
            }
#pragma unroll
            for (int ns = 0; ns < 4; ns++) {
                bc[ns][0] = bn[ns][0];
                bc[ns][1] = bn[ns][1];
            }
        }
#pragma unroll
        for (int ns = 0; ns < 4; ns++) {
            int col0 = n0 + ns * 8 + 2 * kr;
            float bv0 = bd1[col0], bv1 = bd1[col0 + 1];
            int wp = (col0 >> 1);
#pragma unroll
            for (int mt = 0; mt < 3; mt++) {
                int row = wm * 48 + mt * 16 + gr;
                t1S[row * PW + wp] = packbf(silu_f(acc[mt][ns][0] + bv0), silu_f(acc[mt][ns][1] + bv1));
                t1S[(row + 8) * PW + wp] = packbf(silu_f(acc[mt][ns][2] + bv0), silu_f(acc[mt][ns][3] + bv1));
            }
        }
    }
    __syncthreads();

    // phase 4: dp = silu(t1 @ Wd2 + bd2); mask(bf16) *= dp
    {
        int n0 = wn * 16;
        float acc[3][2][4];
#pragma unroll
        for (int mt = 0; mt < 3; mt++)
#pragma unroll
            for (int ns = 0; ns < 2; ns++)
#pragma unroll
                for (int c = 0; c < 4; c++) acc[mt][ns][c] = 0.f;
        uint32_t bc[2][2], bn[2][2];
#pragma unroll
        for (int ns = 0; ns < 2; ns++) {
            bc[ns][0] = g_W2p[(kr) * 128 + n0 + ns * 8 + gr];
            bc[ns][1] = g_W2p[(kr + 4) * 128 + n0 + ns * 8 + gr];
        }
        for (int ks = 0; ks < 16; ks++) {
            int kp0 = ks * 8;
            if (ks < 15) {
#pragma unroll
                for (int ns = 0; ns < 2; ns++) {
                    bn[ns][0] = g_W2p[(kp0 + 8 + kr) * 128 + n0 + ns * 8 + gr];
                    bn[ns][1] = g_W2p[(kp0 + 12 + kr) * 128 + n0 + ns * 8 + gr];
                }
            }
#pragma unroll
            for (int mt = 0; mt < 3; mt++) {
                int row = wm * 48 + mt * 16 + gr;
                uint32_t a0 = t1S[row * PW + kp0 + kr];
                uint32_t a1 = t1S[(row + 8) * PW + kp0 + kr];
                uint32_t a2 = t1S[row * PW + kp0 + kr + 4];
                uint32_t a3 = t1S[(row + 8) * PW + kp0 + kr + 4];
#pragma unroll
                for (int ns = 0; ns < 2; ns++)
                    mma16(acc[mt][ns], a0, a1, a2, a3, bc[ns][0], bc[ns][1]);
            }
#pragma unroll
            for (int ns = 0; ns < 2; ns++) {
                bc[ns][0] = bn[ns][0];
                bc[ns][1] = bn[ns][1];
            }
        }
#pragma unroll
        for (int ns = 0; ns < 2; ns++) {
            int col0 = n0 + ns * 8 + 2 * kr;
            float bv0 = bd2[col0], bv1 = bd2[col0 + 1];
#pragma unroll
            for (int mt = 0; mt < 3; mt++) {
                int row = wm * 48 + mt * 16 + gr;
                size_t idx0 = ((size_t)bi * N + row) * (HID / 2) + (col0 >> 1);
                float2 m0 = unpackbf(g_maskh[idx0]);
                g_maskh[idx0] = packbf(m0.x * silu_f(acc[mt][ns][0] + bv0),
                                       m0.y * silu_f(acc[mt][ns][1] + bv1));
                size_t idx1 = ((size_t)bi * N + row + 8) * (HID / 2) + (col0 >> 1);
                float2 m1 = unpackbf(g_maskh[idx1]);
                g_maskh[idx1] = packbf(m1.x * silu_f(acc[mt][ns][2] + bv0),
                                       m1.y * silu_f(acc[mt][ns][3] + bv1));
            }
        }
    }
}

// ---------------- K6: s += sum_j mask_ij * s1_j ----------------
__global__ void __launch_bounds__(128) k_agg() {
    int i = blockIdx.x, b = blockIdx.y;
    int bi = b * N + i;
    int t = threadIdx.x, c = t & 31, jr = t >> 5;
    __shared__ float4 red[4][32];
    float4 acc = make_float4(0.f, 0.f, 0.f, 0.f);
    const uint32_t* mrow = &g_maskh[(size_t)bi * N * (HID / 2) + c * 2];
#pragma unroll 6
    for (int j = jr; j < N; j += 4) {
        uint2 mp = *(const uint2*)&mrow[(size_t)j * (HID / 2)];
        float2 ma = unpackbf(mp.x), mb = unpackbf(mp.y);
        float4 s4 = *(const float4*)&g_s1[(b * N + j) * HID + c * 4];
        acc.x = fmaf(ma.x, s4.x, acc.x);
        acc.y = fmaf(ma.y, s4.y, acc.y);
        acc.z = fmaf(mb.x, s4.z, acc.z);
        acc.w = fmaf(mb.y, s4.w, acc.w);
    }
    red[jr][c] = acc;
    __syncthreads();
    if (jr == 0) {
        float4 r0 = red[0][c], r1 = red[1][c], r2 = red[2][c], r3 = red[3][c];
        float4 s = *(const float4*)&g_s[bi * HID + c * 4];
        s.x += r0.x + r1.x + r2.x + r3.x;
        s.y += r0.y + r1.y + r2.y + r3.y;
        s.z += r0.z + r1.z + r2.z + r3.z;
        s.w += r0.w + r1.w + r2.w + r3.w;
        *(float4*)&g_s[bi * HID + c * 4] = s;
    }
}

// ---------------- K7: readout ----------------
__global__ void k_read(const int* __restrict__ z, const float* __restrict__ Wout,
                       const float* __restrict__ bout, float* __restrict__ out) {
    int b = blockIdx.x;
    int h = threadIdx.x;
    __shared__ float red[4];
    float acc = 0.0f;
    for (int i = 0; i < N; i++) {
        if (z[b * N + i] != 0) acc += g_s[(b * N + i) * HID + h];
    }
    float p = acc * Wout[h];
    float s = blksum128(p, red);
    if (h == 0) out[b] = s + bout[0];
}

// ---------------- launch ----------------
extern "C" void kernel_launch(void* const* d_in, const int* in_sizes, int n_in,
                              void* d_out, int out_size) {
    const int* z = (const int*)d_in[0];
    const float* pos = (const float*)d_in[1];
    const float* emb = (const float*)d_in[2];
    const float* Wef = (const float*)d_in[3];
    const float* bef = (const float*)d_in[4];
    const float* Ws2v = (const float*)d_in[5];
    const float* bs2v = (const float*)d_in[6];
    const float* Wq = (const float*)d_in[7];
    const float* Wk = (const float*)d_in[8];
    const float* Wd1 = (const float*)d_in[9];
    const float* bd1 = (const float*)d_in[10];
    const float* Wd2 = (const float*)d_in[11];
    const float* bd2 = (const float*)d_in[12];
    const float* Wint = (const float*)d_in[13];
    const float* bint = (const float*)d_in[14];
    const float* Wout = (const float*)d_in[15];
    const float* bout = (const float*)d_in[16];
    float* out = (float*)d_out;

    cudaFuncSetAttribute(k_dir, cudaFuncAttributeMaxDynamicSharedMemorySize, SMEM_DIR_BYTES);

    dim3 g(N, B);
    k_prep<<<(128 * 256 + 128 * 128 + 255) / 256, 256>>>(Wd1, Wd2);
    k_s0<<<BN, 128>>>(z, emb);
    k_geomne<<<g, 128>>>(z, pos, Wef, bef);
    k_lin4<<<BN / LIN_R, 128>>>(Ws2v, bs2v);  // -> g_s1
    k_v<<<g, 128>>>();
    k_qk4<<<BN / LIN_R, 128>>>(Wq, Wk);
    k_dir<<<g, 512, SMEM_DIR_BYTES>>>(bd1, bd2);
    for (int l = 0; l < L; l++) {
        k_lin4<<<BN / LIN_R, 128>>>(Wint + (size_t)l * HID * HID, bint + (size_t)l * HID);
        k_agg<<<g, 128>>>();
    }
    k_read<<<B, 128>>>(z, Wout, bout, out);
}

// round 6
// speedup vs baseline: 3.4048x; 1.2421x over previous
#include <cuda_runtime.h>
#include <cuda_bf16.h>
#include <cstdint>
#include <cstddef>

#define DEVFN __device__ __forceinline__

constexpr int B = 16, N = 96, HID = 128, EF = 32, L = 4;
constexpr int BN = B * N;
constexpr float CUTOFF = 10.0f, RBF_GAMMA = 10.0f;
constexpr float PI_F = 3.14159265358979323846f;

// ---------------- scratch (device globals) ----------------
__device__ uint32_t g_maskh[(size_t)BN * N * (HID / 2)];  // bf16x2 mask
__device__ float g_s0[BN * HID];
__device__ float g_s[BN * HID];
__device__ float g_s1[BN * HID];
__device__ float g_v[BN * 3 * HID];
__device__ float g_qv[BN * 3 * HID];
__device__ float g_kv[BN * 3 * HID];
__device__ float g_ea[BN * N];
__device__ float g_ev[BN * N * 3];
__device__ uint32_t g_W1p[128 * 256];  // Wd1 packed bf16x2 (k-pairs)
__device__ uint32_t g_W2p[128 * 128];  // Wd2 packed bf16x2

DEVFN float silu_f(float x) { return x / (1.0f + __expf(-x)); }

DEVFN void fma4(float4& a, float x, const float4 w) {
    a.x = fmaf(x, w.x, a.x);
    a.y = fmaf(x, w.y, a.y);
    a.z = fmaf(x, w.z, a.z);
    a.w = fmaf(x, w.w, a.w);
}

DEVFN uint32_t packbf(float lo, float hi) {
    uint32_t r;
    asm("cvt.rn.bf16x2.f32 %0, %1, %2;" : "=r"(r) : "f"(hi), "f"(lo));
    return r;
}
DEVFN float2 unpackbf(uint32_t u) {
    __nv_bfloat162 b = *reinterpret_cast<__nv_bfloat162*>(&u);
    return __bfloat1622float2(b);
}

DEVFN void mma16(float c[4], uint32_t a0, uint32_t a1, uint32_t a2, uint32_t a3,
                 uint32_t b0, uint32_t b1) {
    asm volatile(
        "mma.sync.aligned.m16n8k16.row.col.f32.bf16.bf16.f32 "
        "{%0,%1,%2,%3},{%4,%5,%6,%7},{%8,%9},{%0,%1,%2,%3};\n"
        : "+f"(c[0]), "+f"(c[1]), "+f"(c[2]), "+f"(c[3])
        : "r"(a0), "r"(a1), "r"(a2), "r"(a3), "r"(b0), "r"(b1));
}

DEVFN float blksum128(float v, float* red) {
#pragma unroll
    for (int o = 16; o; o >>= 1) v += __shfl_xor_sync(0xffffffffu, v, o);
    if ((threadIdx.x & 31) == 0) red[threadIdx.x >> 5] = v;
    __syncthreads();
    float r = red[0] + red[1] + red[2] + red[3];
    __syncthreads();
    return r;
}

// ---------------- K-1: pack Wd1/Wd2 into bf16x2 k-pair layout ----------------
__global__ void k_prep(const float* __restrict__ Wd1, const float* __restrict__ Wd2) {
    int idx = blockIdx.x * 256 + threadIdx.x;
    if (idx < 128 * 256) {
        int kp = idx >> 8, n = idx & 255;
        g_W1p[idx] = packbf(Wd1[(2 * kp) * 256 + n], Wd1[(2 * kp + 1) * 256 + n]);
    } else {
        int r = idx - 128 * 256;
        if (r < 128 * 128) {
            int kp = r >> 7, n = r & 127;
            g_W2p[r] = packbf(Wd2[(2 * kp) * 128 + n], Wd2[(2 * kp + 1) * 128 + n]);
        }
    }
}

// ---------------- K0: s0 = LN(emb_table[z]) ----------------
__global__ void k_s0(const int* __restrict__ z, const float* __restrict__ emb) {
    int bi = blockIdx.x;
    int h = threadIdx.x;
    __shared__ float red[4];
    int zz = z[bi];
    float e = emb[zz * HID + h];
    float m = blksum128(e, red) * (1.0f / HID);
    float dx = e - m;
    float var = blksum128(dx * dx, red) * (1.0f / HID);
    g_s0[bi * HID + h] = dx * rsqrtf(var + 1e-5f);
}

// ---------------- K1: geometry + ef-proj -> mask(bf16), fused NeighborEmb ----------------
__global__ void __launch_bounds__(128) k_geomne(const int* __restrict__ z,
                                                const float* __restrict__ pos,
                                                const float* __restrict__ Wef,
                                                const float* __restrict__ bef) {
    int i = blockIdx.x, b = blockIdx.y;
    int bi = b * N + i;
    int t = threadIdx.x, w = t >> 5, lane = t & 31;
    __shared__ float wS[EF * HID];
    __shared__ float bS[HID];
    __shared__ float pS[4][HID];
    for (int k = t; k < EF * HID; k += 128) wS[k] = Wef[k];
    bS[t] = bef[t];
    float padi = (z[bi] != 0) ? 1.0f : 0.0f;
    float xi = pos[bi * 3 + 0];
    float yi = pos[bi * 3 + 1];
    float zi = pos[bi * 3 + 2];
    __syncthreads();
    float4 bb = *(const float4*)&bS[lane * 4];
    float4 sacc = make_float4(0.f, 0.f, 0.f, 0.f);
    for (int j = w; j < N; j += 4) {
        float padj = (z[b * N + j] != 0) ? 1.0f : 0.0f;
        float dx = pos[(b * N + j) * 3 + 0] - xi;
        float dy = pos[(b * N + j) * 3 + 1] - yi;
        float dz = pos[(b * N + j) * 3 + 2] - zi;
        float d = sqrtf(dx * dx + dy * dy + dz * dz + 1e-12f);
        float pm = padi * padj * ((i != j) ? 1.0f : 0.0f);
        float ea = (d < CUTOFF) ? 0.5f * (cosf(PI_F * d * (1.0f / CUTOFF)) + 1.0f) * pm : 0.0f;
        float inv = pm / (d + 1e-12f);
        float cc = lane * (CUTOFF / (EF - 1));
        float dd = d - cc;
        float efv = __expf(-RBF_GAMMA * dd * dd) * pm;
        float4 acc = bb;
#pragma unroll
        for (int k = 0; k < EF; k++) {
            float e = __shfl_sync(0xffffffffu, efv, k);
            float4 w4 = *(const float4*)&wS[k * HID + lane * 4];
            fma4(acc, e, w4);
        }
        float4 mv;
        mv.x = silu_f(acc.x) * ea;
        mv.y = silu_f(acc.y) * ea;
        mv.z = silu_f(acc.z) * ea;
        mv.w = silu_f(acc.w) * ea;
        uint2 mp;
        mp.x = packbf(mv.x, mv.y);
        mp.y = packbf(mv.z, mv.w);
        *(uint2*)&g_maskh[((size_t)bi * N + j) * (HID / 2) + lane * 2] = mp;
        float2 ma = unpackbf(mp.x), mb = unpackbf(mp.y);
        float4 s0j = *(const float4*)&g_s0[(b * N + j) * HID + lane * 4];
        sacc.x = fmaf(ma.x, s0j.x, sacc.x);
        sacc.y = fmaf(ma.y, s0j.y, sacc.y);
        sacc.z = fmaf(mb.x, s0j.z, sacc.z);
        sacc.w = fmaf(mb.y, s0j.w, sacc.w);
        if (lane == 0) {
            size_t pidx = (size_t)bi * N + j;
            g_ea[pidx] = ea;
            g_ev[pidx * 3 + 0] = dx * inv;
            g_ev[pidx * 3 + 1] = dy * inv;
            g_ev[pidx * 3 + 2] = dz * inv;
        }
    }
    *(float4*)&pS[w][lane * 4] = sacc;
    __syncthreads();
    float s = g_s0[bi * HID + t] + pS[0][t] + pS[1][t] + pS[2][t] + pS[3][t];
    g_s[bi * HID + t] = s;
}

// ---------------- K2: s1 = silu(LN(s @ W + b)), 4 atoms/block ----------------
// 128 threads = 32 col-groups (4 cols each) x 4 k-quarters. Coalesced float4 weight loads.
constexpr int LIN_R = 4;
__global__ void __launch_bounds__(128) k_lin4(const float* __restrict__ W,
                                              const float* __restrict__ bv) {
    __shared__ float sS[LIN_R][HID];
    __shared__ float redS[4][LIN_R][HID];
    __shared__ float oS[LIN_R][HID];
    __shared__ float mS[LIN_R], vSs[LIN_R];
    int t = threadIdx.x, c = t & 31, q = t >> 5, w = t >> 5, lane = t & 31;
    int base = blockIdx.x * LIN_R;
    for (int k = t; k < LIN_R * HID; k += 128) sS[k >> 7][k & 127] = g_s[base * HID + k];
    __syncthreads();
    float4 acc[LIN_R];
#pragma unroll
    for (int r = 0; r < LIN_R; r++) acc[r] = make_float4(0.f, 0.f, 0.f, 0.f);
    int h0 = q * 32;
#pragma unroll 8
    for (int hh = 0; hh < 32; hh++) {
        int h = h0 + hh;
        float4 wv = *(const float4*)&W[h * HID + c * 4];
#pragma unroll
        for (int r = 0; r < LIN_R; r++) fma4(acc[r], sS[r][h], wv);
    }
#pragma unroll
    for (int r = 0; r < LIN_R; r++) *(float4*)&redS[q][r][c * 4] = acc[r];
    __syncthreads();
#pragma unroll
    for (int r = 0; r < LIN_R; r++)
        oS[r][t] = redS[0][r][t] + redS[1][r][t] + redS[2][r][t] + redS[3][r][t] + bv[t];
    __syncthreads();
    {
        int r = w;
        float x0 = oS[r][lane], x1 = oS[r][lane + 32], x2 = oS[r][lane + 64], x3 = oS[r][lane + 96];
        float s = x0 + x1 + x2 + x3;
#pragma unroll
        for (int o = 16; o; o >>= 1) s += __shfl_xor_sync(0xffffffffu, s, o);
        float mean = s * (1.0f / HID);
        float q0 = x0 - mean, q1 = x1 - mean, q2 = x2 - mean, q3 = x3 - mean;
        float qq = q0 * q0 + q1 * q1 + q2 * q2 + q3 * q3;
#pragma unroll
        for (int o = 16; o; o >>= 1) qq += __shfl_xor_sync(0xffffffffu, qq, o);
        if (lane == 0) {
            mS[r] = mean;
            vSs[r] = rsqrtf(qq * (1.0f / HID) + 1e-5f);
        }
    }
    __syncthreads();
#pragma unroll
    for (int r = 0; r < LIN_R; r++) {
        float val = (oS[r][t] - mS[r]) * vSs[r];
        g_s1[(base + r) * HID + t] = silu_f(val);
    }
}

// ---------------- K3: v_i = sum_j mask_ij * s1_j * ev_ij (256 thr, 8 rows) ----------------
__global__ void __launch_bounds__(256) k_v() {
    int i = blockIdx.x, b = blockIdx.y;
    int bi = b * N + i;
    int t = threadIdx.x, c = t & 31, jr = t >> 5;
    __shared__ float4 red[3][8][32];
    float4 a0 = make_float4(0.f, 0.f, 0.f, 0.f), a1 = a0, a2 = a0;
    const uint32_t* mrow = &g_maskh[(size_t)bi * N * (HID / 2) + c * 2];
    const float* evrow = &g_ev[(size_t)bi * N * 3];
#pragma unroll 4
    for (int j = jr; j < N; j += 8) {
        uint2 mp = *(const uint2*)&mrow[(size_t)j * (HID / 2)];
        float2 ma = unpackbf(mp.x), mb = unpackbf(mp.y);
        float4 s4 = *(const float4*)&g_s1[(b * N + j) * HID + c * 4];
        float e0 = evrow[j * 3 + 0], e1 = evrow[j * 3 + 1], e2 = evrow[j * 3 + 2];
        float4 wv;
        wv.x = ma.x * s4.x;
        wv.y = ma.y * s4.y;
        wv.z = mb.x * s4.z;
        wv.w = mb.y * s4.w;
        fma4(a0, e0, wv);
        fma4(a1, e1, wv);
        fma4(a2, e2, wv);
    }
    red[0][jr][c] = a0;
    red[1][jr][c] = a1;
    red[2][jr][c] = a2;
    __syncthreads();
    if (t < 96) {
        int dim = t >> 5;
        float4 s = make_float4(0.f, 0.f, 0.f, 0.f);
#pragma unroll
        for (int r = 0; r < 8; r++) {
            float4 p = red[dim][r][c];
            s.x += p.x;
            s.y += p.y;
            s.z += p.z;
            s.w += p.w;
        }
        *(float4*)&g_v[(bi * 3 + dim) * HID + c * 4] = s;
    }
}

// ---------------- K4: qv/kv, 2 atoms/block, coalesced float4 weight loads ----------------
constexpr int QK_R = 2;
__global__ void __launch_bounds__(128) k_qk4(const float* __restrict__ Wq,
                                             const float* __restrict__ Wk) {
    __shared__ float vS[QK_R][3 * HID];
    __shared__ float redq[4][QK_R][3][HID];
    __shared__ float redk[4][QK_R][3][HID];
    int t = threadIdx.x, c = t & 31, q = t >> 5;
    int base = blockIdx.x * QK_R;
    for (int k = t; k < QK_R * 3 * HID; k += 128) vS[k / (3 * HID)][k % (3 * HID)] = g_v[base * 3 * HID + k];
    __syncthreads();
    float4 aq[QK_R][3], ak[QK_R][3];
#pragma unroll
    for (int r = 0; r < QK_R; r++)
#pragma unroll
        for (int k3 = 0; k3 < 3; k3++) {
            aq[r][k3] = make_float4(0.f, 0.f, 0.f, 0.f);
            ak[r][k3] = make_float4(0.f, 0.f, 0.f, 0.f);
        }
    int h0 = q * 32;
#pragma unroll 4
    for (int hh = 0; hh < 32; hh++) {
        int h = h0 + hh;
        float4 wq = *(const float4*)&Wq[h * HID + c * 4];
        float4 wk = *(const float4*)&Wk[h * HID + c * 4];
#pragma unroll
        for (int r = 0; r < QK_R; r++)
#pragma unroll
            for (int k3 = 0; k3 < 3; k3++) {
                float vv = vS[r][k3 * HID + h];
                fma4(aq[r][k3], vv, wq);
                fma4(ak[r][k3], vv, wk);
            }
    }
#pragma unroll
    for (int r = 0; r < QK_R; r++)
#pragma unroll
        for (int k3 = 0; k3 < 3; k3++) {
            *(float4*)&redq[q][r][k3][c * 4] = aq[r][k3];
            *(float4*)&redk[q][r][k3][c * 4] = ak[r][k3];
        }
    __syncthreads();
    for (int k = t; k < QK_R * 3 * HID; k += 128) {
        int r = k / (3 * HID);
        int rem = k % (3 * HID);
        int k3 = rem / HID, col = rem % HID;
        float sq = redq[0][r][k3][col] + redq[1][r][k3][col] + redq[2][r][k3][col] + redq[3][r][k3][col];
        float sk = redk[0][r][k3][col] + redk[1][r][k3][col] + redk[2][r][k3][col] + redk[3][r][k3][col];
        g_qv[((base + r) * 3 + k3) * HID + col] = sq;
        g_kv[((base + r) * 3 + k3) * HID + col] = sk;
    }
}

// ---------------- K5: fused directional MLP, bf16 mma, 48-row half-tiles ----------------
constexpr int JH = 48;  // rows per CTA (half tile)
constexpr int PW = 132;
constexpr int SMEM_DIR_BYTES = 2 * JH * PW * 4;  // ~50.7 KB dynamic

__global__ void __launch_bounds__(256) k_dir(const float* __restrict__ bd1,
                                             const float* __restrict__ bd2) {
    int i = blockIdx.x, b = blockIdx.y, half = blockIdx.z;
    int bi = b * N + i;
    int j0 = half * JH;
    int t = threadIdx.x, w = t >> 5, lane = t & 31;
    int gr = lane >> 2, kr = lane & 3;
    extern __shared__ float sm[];
    uint32_t* dirfS = (uint32_t*)sm;      // JH x PW bf16x2
    uint32_t* t1S = dirfS + JH * PW;      // JH x PW bf16x2
    __shared__ float vS[3 * HID], kvS[3 * HID];
    __shared__ float eaS[JH], evS[3 * JH];

    for (int k = t; k < 3 * HID; k += 256) {
        vS[k] = g_v[bi * 3 * HID + k];
        kvS[k] = g_kv[bi * 3 * HID + k];
    }
    if (t < JH) eaS[t] = g_ea[(size_t)bi * N + j0 + t];
    if (t < 3 * JH) evS[t] = g_ev[(size_t)bi * N * 3 + 3 * j0 + t];
    __syncthreads();

    // dirf = concat(dir2, dir3) * ea, packed bf16x2 (h pairs)
    for (int e = t; e < JH * 64; e += 256) {
        int jl = e >> 6, hp = e & 63;
        int h = hp * 2;
        float e0 = evS[jl * 3 + 0], e1 = evS[jl * 3 + 1], e2 = evS[jl * 3 + 2];
        float ea = eaS[jl];
        float d2a = (vS[h] * e0 + vS[HID + h] * e1 + vS[2 * HID + h] * e2) * ea;
        float d2b = (vS[h + 1] * e0 + vS[HID + h + 1] * e1 + vS[2 * HID + h + 1] * e2) * ea;
        const float* qj = &g_qv[(size_t)(b * N + j0 + jl) * 3 * HID + h];
        float d3a = (qj[0] * kvS[h] + qj[HID] * kvS[HID + h] + qj[2 * HID] * kvS[2 * HID + h]) * ea;
        float d3b = (qj[1] * kvS[h + 1] + qj[HID + 1] * kvS[HID + h + 1] +
                     qj[2 * HID + 1] * kvS[2 * HID + h + 1]) * ea;
        dirfS[jl * PW + hp] = packbf(d2a, d2b);
        dirfS[jl * PW + 64 + hp] = packbf(d3a, d3b);
    }
    __syncthreads();

    // phase 3: t1 = silu(dirf(48x256) @ Wd1 + bd1); warp w owns 32 cols
    {
        int n0 = w * 32;
        float acc[3][4][4];
#pragma unroll
        for (int mt = 0; mt < 3; mt++)
#pragma unroll
            for (int ns = 0; ns < 4; ns++)
#pragma unroll
                for (int c = 0; c < 4; c++) acc[mt][ns][c] = 0.f;
        uint32_t bc[4][2], bn[4][2];
#pragma unroll
        for (int ns = 0; ns < 4; ns++) {
            bc[ns][0] = g_W1p[(kr) * 256 + n0 + ns * 8 + gr];
            bc[ns][1] = g_W1p[(kr + 4) * 256 + n0 + ns * 8 + gr];
        }
        for (int ks = 0; ks < 16; ks++) {
            int kp0 = ks * 8;
            if (ks < 15) {
#pragma unroll
                for (int ns = 0; ns < 4; ns++) {
                    bn[ns][0] = g_W1p[(kp0 + 8 + kr) * 256 + n0 + ns * 8 + gr];
                    bn[ns][1] = g_W1p[(kp0 + 12 + kr) * 256 + n0 + ns * 8 + gr];
                }
            }
#pragma unroll
            for (int mt = 0; mt < 3; mt++) {
                int row = mt * 16 + gr;
                uint32_t a0 = dirfS[row * PW + kp0 + kr];
                uint32_t a1 = dirfS[(row + 8) * PW + kp0 + kr];
                uint32_t a2 = dirfS[row * PW + kp0 + kr + 4];
                uint32_t a3 = dirfS[(row + 8) * PW + kp0 + kr + 4];
#pragma unroll
                for (int ns = 0; ns < 4; ns++)
                    mma16(acc[mt][ns], a0, a1, a2, a3, bc[ns][0], bc[ns][1]);
            }
#pragma unroll
            for (int ns = 0; ns < 4; ns++) {
                bc[ns][0] = bn[ns][0];
                bc[ns][1] = bn[ns][1];
            }
        }
#pragma unroll
        for (int ns = 0; ns < 4; ns++) {
            int col0 = n0 + ns * 8 + 2 * kr;
            float bv0 = bd1[col0], bv1 = bd1[col0 + 1];
            int wp = (col0 >> 1);
#pragma unroll
            for (int mt = 0; mt < 3; mt++) {
                int row = mt * 16 + gr;
                t1S[row * PW + wp] = packbf(silu_f(acc[mt][ns][0] + bv0), silu_f(acc[mt][ns][1] + bv1));
                t1S[(row + 8) * PW + wp] = packbf(silu_f(acc[mt][ns][2] + bv0), silu_f(acc[mt][ns][3] + bv1));
            }
        }
    }
    __syncthreads();

    // phase 4: dp = silu(t1(48x256) @ Wd2 + bd2); mask(bf16) *= dp; warp owns 16 cols
    {
        int n0 = w * 16;
        float acc[3][2][4];
#pragma unroll
        for (int mt = 0; mt < 3; mt++)
#pragma unroll
            for (int ns = 0; ns < 2; ns++)
#pragma unroll
                for (int c = 0; c < 4; c++) acc[mt][ns][c] = 0.f;
        uint32_t bc[2][2], bn[2][2];
#pragma unroll
        for (int ns = 0; ns < 2; ns++) {
            bc[ns][0] = g_W2p[(kr) * 128 + n0 + ns * 8 + gr];
            bc[ns][1] = g_W2p[(kr + 4) * 128 + n0 + ns * 8 + gr];
        }
        for (int ks = 0; ks < 16; ks++) {
            int kp0 = ks * 8;
            if (ks < 15) {
#pragma unroll
                for (int ns = 0; ns < 2; ns++) {
                    bn[ns][0] = g_W2p[(kp0 + 8 + kr) * 128 + n0 + ns * 8 + gr];
                    bn[ns][1] = g_W2p[(kp0 + 12 + kr) * 128 + n0 + ns * 8 + gr];
                }
            }
#pragma unroll
            for (int mt = 0; mt < 3; mt++) {
                int row = mt * 16 + gr;
                uint32_t a0 = t1S[row * PW + kp0 + kr];
                uint32_t a1 = t1S[(row + 8) * PW + kp0 + kr];
                uint32_t a2 = t1S[row * PW + kp0 + kr + 4];
                uint32_t a3 = t1S[(row + 8) * PW + kp0 + kr + 4];
#pragma unroll
                for (int ns = 0; ns < 2; ns++)
                    mma16(acc[mt][ns], a0, a1, a2, a3, bc[ns][0], bc[ns][1]);
            }
#pragma unroll
            for (int ns = 0; ns < 2; ns++) {
                bc[ns][0] = bn[ns][0];
                bc[ns][1] = bn[ns][1];
            }
        }
#pragma unroll
        for (int ns = 0; ns < 2; ns++) {
            int col0 = n0 + ns * 8 + 2 * kr;
            float bv0 = bd2[col0], bv1 = bd2[col0 + 1];
#pragma unroll
            for (int mt = 0; mt < 3; mt++) {
                int row = mt * 16 + gr;
                size_t idx0 = ((size_t)bi * N + j0 + row) * (HID / 2) + (col0 >> 1);
                float2 m0 = unpackbf(g_maskh[idx0]);
                g_maskh[idx0] = packbf(m0.x * silu_f(acc[mt][ns][0] + bv0),
                                       m0.y * silu_f(acc[mt][ns][1] + bv1));
                size_t idx1 = ((size_t)bi * N + j0 + row + 8) * (HID / 2) + (col0 >> 1);
                float2 m1 = unpackbf(g_maskh[idx1]);
                g_maskh[idx1] = packbf(m1.x * silu_f(acc[mt][ns][2] + bv0),
                                       m1.y * silu_f(acc[mt][ns][3] + bv1));
            }
        }
    }
}

// ---------------- K6: s += sum_j mask_ij * s1_j (256 thr, 8 rows) ----------------
__global__ void __launch_bounds__(256) k_agg() {
    int i = blockIdx.x, b = blockIdx.y;
    int bi = b * N + i;
    int t = threadIdx.x, c = t & 31, jr = t >> 5;
    __shared__ float4 red[8][32];
    float4 acc = make_float4(0.f, 0.f, 0.f, 0.f);
    const uint32_t* mrow = &g_maskh[(size_t)bi * N * (HID / 2) + c * 2];
#pragma unroll 4
    for (int j = jr; j < N; j += 8) {
        uint2 mp = *(const uint2*)&mrow[(size_t)j * (HID / 2)];
        float2 ma = unpackbf(mp.x), mb = unpackbf(mp.y);
        float4 s4 = *(const float4*)&g_s1[(b * N + j) * HID + c * 4];
        acc.x = fmaf(ma.x, s4.x, acc.x);
        acc.y = fmaf(ma.y, s4.y, acc.y);
        acc.z = fmaf(mb.x, s4.z, acc.z);
        acc.w = fmaf(mb.y, s4.w, acc.w);
    }
    red[jr][c] = acc;
    __syncthreads();
    if (jr == 0) {
        float4 s = *(const float4*)&g_s[bi * HID + c * 4];
#pragma unroll
        for (int r = 0; r < 8; r++) {
            float4 p = red[r][c];
            s.x += p.x;
            s.y += p.y;
            s.z += p.z;
            s.w += p.w;
        }
        *(float4*)&g_s[bi * HID + c * 4] = s;
    }
}

// ---------------- K7: readout ----------------
__global__ void k_read(const int* __restrict__ z, const float* __restrict__ Wout,
                       const float* __restrict__ bout, float* __restrict__ out) {
    int b = blockIdx.x;
    int h = threadIdx.x;
    __shared__ float red[4];
    float acc = 0.0f;
    for (int i = 0; i < N; i++) {
        if (z[b * N + i] != 0) acc += g_s[(b * N + i) * HID + h];
    }
    float p = acc * Wout[h];
    float s = blksum128(p, red);
    if (h == 0) out[b] = s + bout[0];
}

// ---------------- launch ----------------
extern "C" void kernel_launch(void* const* d_in, const int* in_sizes, int n_in,
                              void* d_out, int out_size) {
    const int* z = (const int*)d_in[0];
    const float* pos = (const float*)d_in[1];
    const float* emb = (const float*)d_in[2];
    const float* Wef = (const float*)d_in[3];
    const float* bef = (const float*)d_in[4];
    const float* Ws2v = (const float*)d_in[5];
    const float* bs2v = (const float*)d_in[6];
    const float* Wq = (const float*)d_in[7];
    const float* Wk = (const float*)d_in[8];
    const float* Wd1 = (const float*)d_in[9];
    const float* bd1 = (const float*)d_in[10];
    const float* Wd2 = (const float*)d_in[11];
    const float* bd2 = (const float*)d_in[12];
    const float* Wint = (const float*)d_in[13];
    const float* bint = (const float*)d_in[14];
    const float* Wout = (const float*)d_in[15];
    const float* bout = (const float*)d_in[16];
    float* out = (float*)d_out;

    cudaFuncSetAttribute(k_dir, cudaFuncAttributeMaxDynamicSharedMemorySize, SMEM_DIR_BYTES);

    dim3 g(N, B);
    dim3 gd(N, B, 2);
    k_prep<<<(128 * 256 + 128 * 128 + 255) / 256, 256>>>(Wd1, Wd2);
    k_s0<<<BN, 128>>>(z, emb);
    k_geomne<<<g, 128>>>(z, pos, Wef, bef);
    k_lin4<<<BN / LIN_R, 128>>>(Ws2v, bs2v);  // -> g_s1
    k_v<<<g, 256>>>();
    k_qk4<<<BN / QK_R, 128>>>(Wq, Wk);
    k_dir<<<gd, 256, SMEM_DIR_BYTES>>>(bd1, bd2);
    for (int l = 0; l < L; l++) {
        k_lin4<<<BN / LIN_R, 128>>>(Wint + (size_t)l * HID * HID, bint + (size_t)l * HID);
        k_agg<<<g, 256>>>();
    }
    k_read<<<B, 128>>>(z, Wout, bout, out);
}